// round 1
// baseline (speedup 1.0000x reference)
#include <cuda_runtime.h>

#define NB   4      // batch
#define CIN  128    // input channels
#define NTOT 2048   // total points
#define NH   4      // heads
#define HD   64     // head dim
#define OUTC 256    // output channels
#define NP   16     // NB*NH

// ---- scratch (device globals; no runtime allocation) ----
__device__ float g_x[NB * CIN * NTOT];                 // scattered input (b,c,n)   4 MB
__device__ float g_q[NP * HD * NTOT];                  // (p,d,n)                   8 MB
__device__ float g_k[NP * HD * NTOT];                  // (p,d,n)                   8 MB
__device__ float g_v[NP * HD * NTOT];                  // (p,d,n)                   8 MB
__device__ float g_e[(size_t)NP * NTOT * NTOT];        // energy (p,i,j)          256 MB
__device__ float g_rm[NP * NTOT];                      // row max
__device__ float g_rs[NP * NTOT];                      // row sum(exp)

// ============================================================
// K1: scatter concat([select, drop]) columns to permuted slots
// ============================================================
__global__ __launch_bounds__(256) void scatter_kernel(
    const float* __restrict__ sel, const float* __restrict__ drp,
    const int* __restrict__ isel, const int* __restrict__ idrp)
{
    int t  = blockIdx.x * 256 + threadIdx.x;   // total = 4*128*2048 = 2^20
    int n2 = t & (NTOT - 1);
    int c  = (t >> 11) & (CIN - 1);
    int b  = t >> 18;
    float v; int dst;
    if (n2 < 1024) {
        v   = sel[((size_t)(b * CIN + c)) * 1024 + n2];
        dst = isel[b * 1024 + n2];
    } else {
        int j = n2 - 1024;
        v   = drp[((size_t)(b * CIN + c)) * 1024 + j];
        dst = idrp[b * 1024 + j];
    }
    g_x[((size_t)(b * CIN + c)) * NTOT + dst] = v;
}

// ============================================================
// K2: projections. ob selects {q,k,v,skip} x 64-row block.
//     q/k/v stored (p, d, n); skip written straight into d_out.
//     CTA: 64 out-rows x 128 n-cols, K chunks of 32.
// ============================================================
__global__ __launch_bounds__(256) void proj_kernel(
    const float* __restrict__ pcd,
    const float* __restrict__ Wq, const float* __restrict__ Wk,
    const float* __restrict__ Wv, const float* __restrict__ Wskip,
    float* __restrict__ out)
{
    __shared__ float Ws[64][33];    // padded: conflict-free column reads
    __shared__ float Xs[32][128];
    int b  = blockIdx.z, ob = blockIdx.y, nb = blockIdx.x;
    int m  = ob >> 2;                              // 0=q 1=k 2=v 3=skip
    const float* W = (m == 0 ? Wq : m == 1 ? Wk : m == 2 ? Wv : Wskip) + (ob & 3) * 64 * CIN;
    const float* X = (m == 3 ? pcd : (const float*)g_x) + (size_t)b * CIN * NTOT + nb * 128;
    int t = threadIdx.x, tx = t & 15, ty = t >> 4;
    float acc[4][8] = {};

    for (int k0 = 0; k0 < CIN; k0 += 32) {
        #pragma unroll
        for (int l = 0; l < 8; ++l) {              // Ws: 64x32 scalars
            int idx = t + l * 256;
            int r = idx >> 5, c = idx & 31;
            Ws[r][c] = W[r * CIN + k0 + c];
        }
        #pragma unroll
        for (int l = 0; l < 4; ++l) {              // Xs: 32x128 via float4
            int idx = t + l * 256;
            int r = idx >> 5, c4 = (idx & 31) * 4;
            *(float4*)&Xs[r][c4] = *(const float4*)(X + (size_t)(k0 + r) * NTOT + c4);
        }
        __syncthreads();
        #pragma unroll 8
        for (int k = 0; k < 32; ++k) {
            float wv[4], xv[8];
            #pragma unroll
            for (int j = 0; j < 4; ++j) wv[j] = Ws[ty + j * 16][k];
            #pragma unroll
            for (int i = 0; i < 8; ++i) xv[i] = Xs[k][tx + i * 16];
            #pragma unroll
            for (int j = 0; j < 4; ++j)
                #pragma unroll
                for (int i = 0; i < 8; ++i)
                    acc[j][i] += wv[j] * xv[i];
        }
        __syncthreads();
    }

    int n0 = nb * 128;
    if (m < 3) {
        float* dst = (m == 0 ? g_q : m == 1 ? g_k : g_v);
        int h = ob & 3;                            // 64 rows == one head's d-range
        #pragma unroll
        for (int j = 0; j < 4; ++j) {
            int d = ty + j * 16;
            float* row = dst + ((size_t)((b * NH + h) * HD + d)) * NTOT + n0;
            #pragma unroll
            for (int i = 0; i < 8; ++i) row[tx + i * 16] = acc[j][i];
        }
    } else {
        #pragma unroll
        for (int j = 0; j < 4; ++j) {
            int o = (ob & 3) * 64 + ty + j * 16;
            float* row = out + ((size_t)(b * OUTC + o)) * NTOT + n0;
            #pragma unroll
            for (int i = 0; i < 8; ++i) row[tx + i * 16] = acc[j][i];
        }
    }
}

// ============================================================
// K3: E[p,i,j] = 0.125 * sum_d Q[p,d,i] * K[p,d,j]
//     CTA: 128x128 tile, 8x8 per thread, K chunks of 32.
// ============================================================
__global__ __launch_bounds__(256, 2) void qk_kernel()
{
    __shared__ float Qs[32][128];
    __shared__ float Ks[32][128];
    int p = blockIdx.z, it = blockIdx.y, jt = blockIdx.x;
    int t = threadIdx.x, tx = t & 15, ty = t >> 4;
    const float* Qb = g_q + (size_t)p * HD * NTOT + it * 128;
    const float* Kb = g_k + (size_t)p * HD * NTOT + jt * 128;
    float acc[8][8] = {};

    for (int k0 = 0; k0 < HD; k0 += 32) {
        #pragma unroll
        for (int l = 0; l < 4; ++l) {
            int idx = t + l * 256;
            int r = idx >> 5, c4 = (idx & 31) * 4;
            *(float4*)&Qs[r][c4] = *(const float4*)(Qb + (size_t)(k0 + r) * NTOT + c4);
            *(float4*)&Ks[r][c4] = *(const float4*)(Kb + (size_t)(k0 + r) * NTOT + c4);
        }
        __syncthreads();
        #pragma unroll 8
        for (int k = 0; k < 32; ++k) {
            float qv[8], kv[8];
            #pragma unroll
            for (int u = 0; u < 8; ++u) qv[u] = Qs[k][ty + u * 16];
            #pragma unroll
            for (int w = 0; w < 8; ++w) kv[w] = Ks[k][tx + w * 16];
            #pragma unroll
            for (int u = 0; u < 8; ++u)
                #pragma unroll
                for (int w = 0; w < 8; ++w)
                    acc[u][w] += qv[u] * kv[w];
        }
        __syncthreads();
    }

    float* E = g_e + ((size_t)(p * NTOT + it * 128)) * NTOT + jt * 128;
    #pragma unroll
    for (int u = 0; u < 8; ++u) {
        size_t roff = (size_t)(ty + u * 16) * NTOT;
        #pragma unroll
        for (int w = 0; w < 8; ++w)
            E[roff + tx + w * 16] = acc[u][w] * 0.125f;
    }
}

// ============================================================
// K4: per-row online max + sum(exp) over 2048 energies
//     one warp per row, float4 strided reads
// ============================================================
__global__ __launch_bounds__(256) void stats_kernel()
{
    int row  = blockIdx.x * 8 + (threadIdx.x >> 5);   // 32768 rows total
    int lane = threadIdx.x & 31;
    const float4* E4 = (const float4*)(g_e + (size_t)row * NTOT);
    float mx = -3.0e38f, sm = 0.f;
    for (int j = lane; j < NTOT / 4; j += 32) {
        float4 e = E4[j];
        float m0 = fmaxf(fmaxf(e.x, e.y), fmaxf(e.z, e.w));
        float nm = fmaxf(mx, m0);
        sm = sm * __expf(mx - nm)
           + __expf(e.x - nm) + __expf(e.y - nm)
           + __expf(e.z - nm) + __expf(e.w - nm);
        mx = nm;
    }
    #pragma unroll
    for (int o = 16; o; o >>= 1) {
        float om = __shfl_xor_sync(0xffffffffu, mx, o);
        float os = __shfl_xor_sync(0xffffffffu, sm, o);
        float nm = fmaxf(mx, om);
        sm = sm * __expf(mx - nm) + os * __expf(om - nm);
        mx = nm;
    }
    if (lane == 0) { g_rm[row] = mx; g_rs[row] = sm; }
}

// ============================================================
// K5: out[p*64+d, i] += (1/l_i) * sum_j exp(E[i,j]-m_i) * V[d,j]
//     CTA: 128 i-rows x all 64 d, j chunks of 32. exp on-the-fly.
// ============================================================
__global__ __launch_bounds__(256) void av_kernel(float* __restrict__ out)
{
    __shared__ float Ps[128][33];   // padded: conflict-free row-major column reads
    __shared__ float Vs[64][33];
    __shared__ float rms[128];
    __shared__ float rli[128];
    int p = blockIdx.y, it = blockIdx.x;
    int t = threadIdx.x, tx = t & 15, ty = t >> 4;
    int i0 = it * 128;
    if (t < 128) {
        rms[t] = g_rm[p * NTOT + i0 + t];
        rli[t] = 1.0f / g_rs[p * NTOT + i0 + t];
    }
    __syncthreads();

    float acc[8][4] = {};
    const float* Eb = g_e + ((size_t)(p * NTOT + i0)) * NTOT;
    const float* Vb = g_v + (size_t)p * HD * NTOT;

    for (int j0 = 0; j0 < NTOT; j0 += 32) {
        #pragma unroll
        for (int l = 0; l < 4; ++l) {              // Ps: 128x32 with exp
            int idx = t + l * 256;
            int r = idx >> 3, c4 = (idx & 7) * 4;
            float4 e = *(const float4*)(Eb + (size_t)r * NTOT + j0 + c4);
            float m = rms[r];
            Ps[r][c4 + 0] = __expf(e.x - m);
            Ps[r][c4 + 1] = __expf(e.y - m);
            Ps[r][c4 + 2] = __expf(e.z - m);
            Ps[r][c4 + 3] = __expf(e.w - m);
        }
        #pragma unroll
        for (int l = 0; l < 2; ++l) {              // Vs: 64x32
            int idx = t + l * 256;
            int r = idx >> 3, c4 = (idx & 7) * 4;
            float4 v = *(const float4*)(Vb + (size_t)r * NTOT + j0 + c4);
            Vs[r][c4 + 0] = v.x; Vs[r][c4 + 1] = v.y;
            Vs[r][c4 + 2] = v.z; Vs[r][c4 + 3] = v.w;
        }
        __syncthreads();
        #pragma unroll 8
        for (int j = 0; j < 32; ++j) {
            float pv[8], vv[4];
            #pragma unroll
            for (int u = 0; u < 8; ++u) pv[u] = Ps[ty + u * 16][j];
            #pragma unroll
            for (int w = 0; w < 4; ++w) vv[w] = Vs[tx + w * 16][j];
            #pragma unroll
            for (int u = 0; u < 8; ++u)
                #pragma unroll
                for (int w = 0; w < 4; ++w)
                    acc[u][w] += pv[u] * vv[w];
        }
        __syncthreads();
    }

    // epilogue: add into skip already resident in d_out
    #pragma unroll
    for (int u = 0; u < 8; ++u) {
        int i = ty + u * 16;
        float inv = rli[i];
        #pragma unroll
        for (int w = 0; w < 4; ++w) {
            int d = tx + w * 16;
            size_t o = ((size_t)(p * HD + d)) * NTOT + i0 + i;
            out[o] += acc[u][w] * inv;
        }
    }
}

// ============================================================
extern "C" void kernel_launch(void* const* d_in, const int* in_sizes, int n_in,
                              void* d_out, int out_size)
{
    const float* pcd   = (const float*)d_in[0];
    const float* sel   = (const float*)d_in[1];
    const float* drp   = (const float*)d_in[2];
    const int*   isel  = (const int*)d_in[3];
    const int*   idrp  = (const int*)d_in[4];
    const float* Wq    = (const float*)d_in[5];
    const float* Wk    = (const float*)d_in[6];
    const float* Wv    = (const float*)d_in[7];
    const float* Wskip = (const float*)d_in[8];
    float* out = (float*)d_out;

    scatter_kernel<<<(NB * CIN * NTOT) / 256, 256>>>(sel, drp, isel, idrp);
    proj_kernel<<<dim3(16, 16, NB), 256>>>(pcd, Wq, Wk, Wv, Wskip, out);
    qk_kernel<<<dim3(16, 16, NP), 256>>>();
    stats_kernel<<<(NP * NTOT) / 8, 256>>>();
    av_kernel<<<dim3(16, NP), 256>>>(out);
}

// round 3
// speedup vs baseline: 3.1573x; 3.1573x over previous
#include <cuda_runtime.h>
#include <cuda_bf16.h>
#include <cstdint>

#define NB   4
#define CIN  128
#define NTOT 2048
#define NH   4
#define HD   64
#define OUTC 256
#define NP   16
#define NCHUNK 32          // 2048 / 64 j-chunks

// ---------------- scratch ----------------
__device__ float g_x[NB * CIN * NTOT];                 // scattered input
__device__ __nv_bfloat16 g_q[NP * NTOT * 128];         // (p,n,[hi64|lo64]), pre-scaled 1/8
__device__ __nv_bfloat16 g_k[NP * NTOT * 128];         // (p,n,[hi64|lo64])
__device__ __nv_bfloat16 g_vh[NP * HD * NTOT];         // (p,d,n) hi
__device__ __nv_bfloat16 g_vl[NP * HD * NTOT];         // (p,d,n) lo

// ---------------- helpers ----------------
__device__ __forceinline__ uint32_t smem_u32(const void* p) {
    uint32_t a;
    asm("{ .reg .u64 t; cvta.to.shared.u64 t, %1; cvt.u32.u64 %0, t; }" : "=r"(a) : "l"(p));
    return a;
}
__device__ __forceinline__ void ldsm_x4(uint32_t& r0, uint32_t& r1, uint32_t& r2, uint32_t& r3,
                                        uint32_t addr) {
    asm volatile("ldmatrix.sync.aligned.m8n8.x4.shared.b16 {%0,%1,%2,%3}, [%4];"
                 : "=r"(r0), "=r"(r1), "=r"(r2), "=r"(r3) : "r"(addr));
}
__device__ __forceinline__ void mma16816(float* d, const uint32_t* a, uint32_t b0, uint32_t b1) {
    asm volatile("mma.sync.aligned.m16n8k16.row.col.f32.bf16.bf16.f32 "
                 "{%0,%1,%2,%3}, {%4,%5,%6,%7}, {%8,%9}, {%0,%1,%2,%3};"
                 : "+f"(d[0]), "+f"(d[1]), "+f"(d[2]), "+f"(d[3])
                 : "r"(a[0]), "r"(a[1]), "r"(a[2]), "r"(a[3]), "r"(b0), "r"(b1));
}

// ============================================================
// K1: scatter
// ============================================================
__global__ __launch_bounds__(256) void scatter_kernel(
    const float* __restrict__ sel, const float* __restrict__ drp,
    const int* __restrict__ isel, const int* __restrict__ idrp)
{
    int t  = blockIdx.x * 256 + threadIdx.x;
    int n2 = t & (NTOT - 1);
    int c  = (t >> 11) & (CIN - 1);
    int b  = t >> 18;
    float v; int dst;
    if (n2 < 1024) {
        v   = sel[((size_t)(b * CIN + c)) * 1024 + n2];
        dst = isel[b * 1024 + n2];
    } else {
        int j = n2 - 1024;
        v   = drp[((size_t)(b * CIN + c)) * 1024 + j];
        dst = idrp[b * 1024 + j];
    }
    g_x[((size_t)(b * CIN + c)) * NTOT + dst] = v;
}

// ============================================================
// K2: projections -> bf16 hi/lo (+ fp32 skip into d_out)
// ============================================================
__global__ __launch_bounds__(256) void proj_kernel(
    const float* __restrict__ pcd,
    const float* __restrict__ Wq, const float* __restrict__ Wk,
    const float* __restrict__ Wv, const float* __restrict__ Wskip,
    float* __restrict__ out)
{
    __shared__ __align__(16) char sh[34816];
    float (*Ws)[33]  = (float (*)[33])sh;            // 64 x 33
    float (*Xs)[128] = (float (*)[128])(sh + 8448);  // 32 x 128

    int b  = blockIdx.z, ob = blockIdx.y, nb = blockIdx.x;
    int m  = ob >> 2;                                // 0=q 1=k 2=v 3=skip
    int h  = ob & 3;
    const float* W = (m == 0 ? Wq : m == 1 ? Wk : m == 2 ? Wv : Wskip) + h * 64 * CIN;
    const float* X = (m == 3 ? pcd : (const float*)g_x) + (size_t)b * CIN * NTOT + nb * 128;
    int t = threadIdx.x, tx = t & 15, ty = t >> 4;
    float acc[4][8] = {};

    for (int k0 = 0; k0 < CIN; k0 += 32) {
        #pragma unroll
        for (int l = 0; l < 8; ++l) {
            int idx = t + l * 256;
            int r = idx >> 5, c = idx & 31;
            Ws[r][c] = W[r * CIN + k0 + c];
        }
        #pragma unroll
        for (int l = 0; l < 4; ++l) {
            int idx = t + l * 256;
            int r = idx >> 5, c4 = (idx & 31) * 4;
            *(float4*)&Xs[r][c4] = *(const float4*)(X + (size_t)(k0 + r) * NTOT + c4);
        }
        __syncthreads();
        #pragma unroll 8
        for (int k = 0; k < 32; ++k) {
            float wv[4], xv[8];
            #pragma unroll
            for (int j = 0; j < 4; ++j) wv[j] = Ws[ty + j * 16][k];
            #pragma unroll
            for (int i = 0; i < 8; ++i) xv[i] = Xs[k][tx + i * 16];
            #pragma unroll
            for (int j = 0; j < 4; ++j)
                #pragma unroll
                for (int i = 0; i < 8; ++i)
                    acc[j][i] += wv[j] * xv[i];
        }
        __syncthreads();
    }

    int n0 = nb * 128;
    int p  = b * NH + h;

    if (m == 3) {                                    // skip -> d_out (fp32)
        #pragma unroll
        for (int j = 0; j < 4; ++j) {
            int o = h * 64 + ty + j * 16;
            float* row = out + ((size_t)(b * OUTC + o)) * NTOT + n0;
            #pragma unroll
            for (int i = 0; i < 8; ++i) row[tx + i * 16] = acc[j][i];
        }
    } else if (m == 2) {                             // v -> (p,d,n) hi/lo
        #pragma unroll
        for (int j = 0; j < 4; ++j) {
            int d = ty + j * 16;
            size_t base = (size_t)(p * HD + d) * NTOT + n0;
            #pragma unroll
            for (int i = 0; i < 8; ++i) {
                float x = acc[j][i];
                __nv_bfloat16 hi = __float2bfloat16(x);
                __nv_bfloat16 lo = __float2bfloat16(x - __bfloat162float(hi));
                g_vh[base + tx + i * 16] = hi;
                g_vl[base + tx + i * 16] = lo;
            }
        }
    } else {                                         // q/k -> (p,n,128) via smem transpose
        float scale = (m == 0) ? 0.125f : 1.0f;
        __syncthreads();
        __nv_bfloat16 (*Sq)[136] = (__nv_bfloat16 (*)[136])sh;   // 128 x 136
        #pragma unroll
        for (int j = 0; j < 4; ++j) {
            int d = ty + j * 16;
            #pragma unroll
            for (int i = 0; i < 8; ++i) {
                int n = tx + i * 16;
                float x = acc[j][i] * scale;
                __nv_bfloat16 hi = __float2bfloat16(x);
                __nv_bfloat16 lo = __float2bfloat16(x - __bfloat162float(hi));
                Sq[n][d]      = hi;
                Sq[n][64 + d] = lo;
            }
        }
        __syncthreads();
        uint32_t* gq = (uint32_t*)((m == 0 ? g_q : g_k) + ((size_t)p * NTOT + n0) * 128);
        #pragma unroll
        for (int l = 0; l < 32; ++l) {
            int idx = t + l * 256;                   // 8192 words
            int n = idx >> 6, w = idx & 63;
            gq[idx] = *(const uint32_t*)&Sq[n][w * 2];
        }
    }
}

// ============================================================
// K3: fused flash attention via mma.sync (bf16 3-term split)
//     grid (16 it, 16 p), 256 threads = 8 warps x 16 rows
// ============================================================
#define QS_OFF 0
#define KS_OFF 34816
#define VS_OFF 52224
#define SMEM_ATTN 69632
#define ROWB 272     // 136 bf16 per smem row (16B-pad keeps ldmatrix conflict-free)

__global__ __launch_bounds__(256, 2) void attn_kernel(float* __restrict__ out)
{
    extern __shared__ __align__(1024) char smem[];
    uint32_t sb = smem_u32(smem);
    int tid = threadIdx.x, wid = tid >> 5, lane = tid & 31;
    int it = blockIdx.x, p = blockIdx.y;
    int b = p >> 2, h = p & 3;

    // ---- load Q tile: 128 rows x 256B ----
    {
        const uint4* gq = (const uint4*)(g_q + ((size_t)p * NTOT + it * 128) * 128);
        #pragma unroll
        for (int l = 0; l < 8; ++l) {
            int idx = tid + l * 256;                 // 2048 x 16B
            int row = idx >> 4, c16 = idx & 15;
            *(uint4*)(smem + QS_OFF + row * ROWB + c16 * 16) = gq[idx];
        }
    }

    // ldmatrix lane address maps
    int a_row  = lane & 15;                      // A fragment
    int a_k16  = (lane >> 4) * 16;               // bytes (8 bf16)
    int b_row  = (lane & 7) | ((lane & 16) >> 1);// B fragment
    int b_k16  = ((lane >> 3) & 1) * 16;         // bytes
    uint32_t qa = sb + QS_OFF + (wid * 16 + a_row) * ROWB + a_k16;
    uint32_t kb = sb + KS_OFF + b_row * ROWB + b_k16;
    uint32_t vb = sb + VS_OFF + b_row * ROWB + b_k16;

    float o[8][4] = {};
    float rsl = 0.f, rsh = 0.f;

    for (int c = 0; c < NCHUNK; ++c) {
        __syncthreads();
        // ---- load K chunk (64 x 256B) + V chunk hi/lo (64 x (128|128)B) ----
        {
            const uint4* gk = (const uint4*)(g_k + ((size_t)p * NTOT + c * 64) * 128);
            #pragma unroll
            for (int l = 0; l < 4; ++l) {
                int idx = tid + l * 256;             // 1024 x 16B
                int row = idx >> 4, c16 = idx & 15;
                *(uint4*)(smem + KS_OFF + row * ROWB + c16 * 16) = gk[idx];
            }
            #pragma unroll
            for (int l = 0; l < 2; ++l) {
                int idx = tid + l * 256;             // 512 x 16B each
                int d = idx >> 3, u = idx & 7;
                const uint4* vh = (const uint4*)(g_vh + (size_t)(p * HD + d) * NTOT + c * 64);
                const uint4* vl = (const uint4*)(g_vl + (size_t)(p * HD + d) * NTOT + c * 64);
                *(uint4*)(smem + VS_OFF + d * ROWB + u * 16)       = vh[u];
                *(uint4*)(smem + VS_OFF + d * ROWB + 128 + u * 16) = vl[u];
            }
        }
        __syncthreads();

        // ---- S = Qh·Kh + Ql·Kh + Qh·Kl  (128 x 64 per CTA, 16 x 64 per warp) ----
        float s[8][4] = {};
        #pragma unroll
        for (int kt = 0; kt < 4; ++kt) {
            uint32_t aqh[4], aql[4];
            ldsm_x4(aqh[0], aqh[1], aqh[2], aqh[3], qa + kt * 32);
            ldsm_x4(aql[0], aql[1], aql[2], aql[3], qa + 128 + kt * 32);
            #pragma unroll
            for (int nt2 = 0; nt2 < 4; ++nt2) {
                uint32_t bh[4], bl[4];
                uint32_t base = kb + nt2 * (16 * ROWB) + kt * 32;
                ldsm_x4(bh[0], bh[1], bh[2], bh[3], base);
                ldsm_x4(bl[0], bl[1], bl[2], bl[3], base + 128);
                mma16816(s[2 * nt2],     aqh, bh[0], bh[1]);
                mma16816(s[2 * nt2 + 1], aqh, bh[2], bh[3]);
                mma16816(s[2 * nt2],     aql, bh[0], bh[1]);
                mma16816(s[2 * nt2 + 1], aql, bh[2], bh[3]);
                mma16816(s[2 * nt2],     aqh, bl[0], bl[1]);
                mma16816(s[2 * nt2 + 1], aqh, bl[2], bl[3]);
            }
        }

        // ---- exp + bf16 hi/lo pack into A fragments for P·V ----
        uint32_t ph[4][4], pl[4][4];
        #pragma unroll
        for (int kt = 0; kt < 4; ++kt) {
            #pragma unroll
            for (int hf = 0; hf < 2; ++hf) {
                float* sv = s[2 * kt + hf];
                float e0 = __expf(sv[0]), e1 = __expf(sv[1]);
                float e2 = __expf(sv[2]), e3 = __expf(sv[3]);
                rsl += e0 + e1; rsh += e2 + e3;
                uint32_t h01, h23, l01, l23;
                asm("cvt.rn.bf16x2.f32 %0, %1, %2;" : "=r"(h01) : "f"(e1), "f"(e0));
                asm("cvt.rn.bf16x2.f32 %0, %1, %2;" : "=r"(h23) : "f"(e3), "f"(e2));
                float f0 = __uint_as_float(h01 << 16);
                float f1 = __uint_as_float(h01 & 0xffff0000u);
                float f2 = __uint_as_float(h23 << 16);
                float f3 = __uint_as_float(h23 & 0xffff0000u);
                float r0 = e0 - f0, r1 = e1 - f1, r2 = e2 - f2, r3 = e3 - f3;
                asm("cvt.rn.bf16x2.f32 %0, %1, %2;" : "=r"(l01) : "f"(r1), "f"(r0));
                asm("cvt.rn.bf16x2.f32 %0, %1, %2;" : "=r"(l23) : "f"(r3), "f"(r2));
                ph[kt][2 * hf] = h01; ph[kt][2 * hf + 1] = h23;
                pl[kt][2 * hf] = l01; pl[kt][2 * hf + 1] = l23;
            }
        }

        // ---- O += Ph·Vh + Pl·Vh + Ph·Vl ----
        #pragma unroll
        for (int kt = 0; kt < 4; ++kt) {
            #pragma unroll
            for (int nt2 = 0; nt2 < 4; ++nt2) {
                uint32_t bh[4], bl[4];
                uint32_t base = vb + nt2 * (16 * ROWB) + kt * 32;
                ldsm_x4(bh[0], bh[1], bh[2], bh[3], base);
                ldsm_x4(bl[0], bl[1], bl[2], bl[3], base + 128);
                mma16816(o[2 * nt2],     ph[kt], bh[0], bh[1]);
                mma16816(o[2 * nt2 + 1], ph[kt], bh[2], bh[3]);
                mma16816(o[2 * nt2],     pl[kt], bh[0], bh[1]);
                mma16816(o[2 * nt2 + 1], pl[kt], bh[2], bh[3]);
                mma16816(o[2 * nt2],     ph[kt], bl[0], bl[1]);
                mma16816(o[2 * nt2 + 1], ph[kt], bl[2], bl[3]);
            }
        }
    }

    // ---- row-sum reduce across quad, normalize, transpose via smem ----
    #pragma unroll
    for (int off = 1; off < 4; off <<= 1) {
        rsl += __shfl_xor_sync(0xffffffffu, rsl, off);
        rsh += __shfl_xor_sync(0xffffffffu, rsh, off);
    }
    float invl = 1.0f / rsl, invh = 1.0f / rsh;

    __syncthreads();                                 // done with Q/K/V smem
    float* Os = (float*)smem;                        // [64][129]
    int i_lo = wid * 16 + (lane >> 2);
    #pragma unroll
    for (int nt = 0; nt < 8; ++nt) {
        int d0 = nt * 8 + (lane & 3) * 2;
        Os[d0 * 129 + i_lo]           = o[nt][0] * invl;
        Os[(d0 + 1) * 129 + i_lo]     = o[nt][1] * invl;
        Os[d0 * 129 + i_lo + 8]       = o[nt][2] * invh;
        Os[(d0 + 1) * 129 + i_lo + 8] = o[nt][3] * invh;
    }
    __syncthreads();

    #pragma unroll
    for (int l = 0; l < 32; ++l) {
        int idx = tid + l * 256;                     // 8192 elements
        int i = idx & 127, d = idx >> 7;
        size_t go = ((size_t)(b * OUTC + h * HD + d)) * NTOT + it * 128 + i;
        out[go] += Os[d * 129 + i];
    }
}

// ============================================================
extern "C" void kernel_launch(void* const* d_in, const int* in_sizes, int n_in,
                              void* d_out, int out_size)
{
    const float* pcd   = (const float*)d_in[0];
    const float* sel   = (const float*)d_in[1];
    const float* drp   = (const float*)d_in[2];
    const int*   isel  = (const int*)d_in[3];
    const int*   idrp  = (const int*)d_in[4];
    const float* Wq    = (const float*)d_in[5];
    const float* Wk    = (const float*)d_in[6];
    const float* Wv    = (const float*)d_in[7];
    const float* Wskip = (const float*)d_in[8];
    float* out = (float*)d_out;

    cudaFuncSetAttribute(attn_kernel, cudaFuncAttributeMaxDynamicSharedMemorySize, SMEM_ATTN);

    scatter_kernel<<<(NB * CIN * NTOT) / 256, 256>>>(sel, drp, isel, idrp);
    proj_kernel<<<dim3(16, 16, NB), 256>>>(pcd, Wq, Wk, Wv, Wskip, out);
    attn_kernel<<<dim3(16, NP), 256, SMEM_ATTN>>>(out);
}

// round 5
// speedup vs baseline: 3.7235x; 1.1793x over previous
#include <cuda_runtime.h>
#include <cuda_bf16.h>
#include <cstdint>

#define NB   4
#define CIN  128
#define NTOT 2048
#define NH   4
#define HD   64
#define OUTC 256
#define NP   16
#define NCHUNK 32

// ---------------- scratch ----------------
__device__ __nv_bfloat16 g_xh[NB * CIN * NTOT];        // scattered input hi (b,c,n)
__device__ __nv_bfloat16 g_xl[NB * CIN * NTOT];        // scattered input lo
__device__ __nv_bfloat16 g_ph[NB * CIN * NTOT];        // pcd_up hi (b,c,n)
__device__ __nv_bfloat16 g_pl[NB * CIN * NTOT];        // pcd_up lo
__device__ __nv_bfloat16 g_q[NP * NTOT * 128];         // (p,n,[hi64|lo64]) pre-scaled 1/8
__device__ __nv_bfloat16 g_k[NP * NTOT * 128];         // (p,n,[hi64|lo64])
__device__ __nv_bfloat16 g_v[NP * NTOT * 128];         // (p,n,[hi64|lo64])

// ---------------- helpers ----------------
__device__ __forceinline__ uint32_t smem_u32(const void* p) {
    uint32_t a;
    asm("{ .reg .u64 t; cvta.to.shared.u64 t, %1; cvt.u32.u64 %0, t; }" : "=r"(a) : "l"(p));
    return a;
}
__device__ __forceinline__ void ldsm_x4(uint32_t& r0, uint32_t& r1, uint32_t& r2, uint32_t& r3,
                                        uint32_t addr) {
    asm volatile("ldmatrix.sync.aligned.m8n8.x4.shared.b16 {%0,%1,%2,%3}, [%4];"
                 : "=r"(r0), "=r"(r1), "=r"(r2), "=r"(r3) : "r"(addr));
}
__device__ __forceinline__ void ldsm_x4_t(uint32_t& r0, uint32_t& r1, uint32_t& r2, uint32_t& r3,
                                          uint32_t addr) {
    asm volatile("ldmatrix.sync.aligned.m8n8.x4.trans.shared.b16 {%0,%1,%2,%3}, [%4];"
                 : "=r"(r0), "=r"(r1), "=r"(r2), "=r"(r3) : "r"(addr));
}
__device__ __forceinline__ void mma16816(float* d, const uint32_t* a, uint32_t b0, uint32_t b1) {
    asm volatile("mma.sync.aligned.m16n8k16.row.col.f32.bf16.bf16.f32 "
                 "{%0,%1,%2,%3}, {%4,%5,%6,%7}, {%8,%9}, {%0,%1,%2,%3};"
                 : "+f"(d[0]), "+f"(d[1]), "+f"(d[2]), "+f"(d[3])
                 : "r"(a[0]), "r"(a[1]), "r"(a[2]), "r"(a[3]), "r"(b0), "r"(b1));
}
#define CP16(dst, src) asm volatile("cp.async.cg.shared.global [%0], [%1], 16;" :: "r"(dst), "l"(src))
#define CP_COMMIT()    asm volatile("cp.async.commit_group;" ::: "memory")
#define CP_WAIT(n)     asm volatile("cp.async.wait_group %0;" :: "n"(n) : "memory")

__device__ __forceinline__ void split_bf16(float x, __nv_bfloat16& hi, __nv_bfloat16& lo) {
    hi = __float2bfloat16(x);
    lo = __float2bfloat16(x - __bfloat162float(hi));
}

// ============================================================
// K1: scatter concat([select, drop]) -> permuted columns, bf16 hi/lo
// ============================================================
__global__ __launch_bounds__(256) void scatter_kernel(
    const float* __restrict__ sel, const float* __restrict__ drp,
    const int* __restrict__ isel, const int* __restrict__ idrp)
{
    int t  = blockIdx.x * 256 + threadIdx.x;
    int n2 = t & (NTOT - 1);
    int c  = (t >> 11) & (CIN - 1);
    int b  = t >> 18;
    float v; int dst;
    if (n2 < 1024) {
        v   = sel[((size_t)(b * CIN + c)) * 1024 + n2];
        dst = isel[b * 1024 + n2];
    } else {
        int j = n2 - 1024;
        v   = drp[((size_t)(b * CIN + c)) * 1024 + j];
        dst = idrp[b * 1024 + j];
    }
    __nv_bfloat16 hi, lo;
    split_bf16(v, hi, lo);
    size_t off = ((size_t)(b * CIN + c)) * NTOT + dst;
    g_xh[off] = hi;
    g_xl[off] = lo;
}

// ============================================================
// K1b: pcd_up fp32 -> bf16 hi/lo
// ============================================================
__global__ __launch_bounds__(256) void conv_kernel(const float* __restrict__ pcd)
{
    int t = blockIdx.x * 256 + threadIdx.x;        // 262144 float4
    float4 v = ((const float4*)pcd)[t];
    __nv_bfloat16 h0, h1, h2, h3, l0, l1, l2, l3;
    split_bf16(v.x, h0, l0); split_bf16(v.y, h1, l1);
    split_bf16(v.z, h2, l2); split_bf16(v.w, h3, l3);
    __nv_bfloat162* ph = (__nv_bfloat162*)(g_ph + (size_t)t * 4);
    __nv_bfloat162* pl = (__nv_bfloat162*)(g_pl + (size_t)t * 4);
    ph[0] = {h0, h1}; ph[1] = {h2, h3};
    pl[0] = {l0, l1}; pl[1] = {l2, l3};
}

// ============================================================
// K2: projections on tensor cores (3-term bf16 split)
//     grid (nb=16, ob=16, b=4), 256 thr; out tile 64(o) x 128(n), k=128
// ============================================================
#define PWH 0
#define PWL 17408
#define PXH 34816
#define PXL 69632
#define SMEM_PROJ 104448

__global__ __launch_bounds__(256, 2) void proj_kernel(
    const float* __restrict__ Wq, const float* __restrict__ Wk,
    const float* __restrict__ Wv, const float* __restrict__ Wskip,
    float* __restrict__ out)
{
    extern __shared__ __align__(1024) char smem[];
    uint32_t sb = smem_u32(smem);
    int tid = threadIdx.x, wid = tid >> 5, lane = tid & 31;
    int nb = blockIdx.x, ob = blockIdx.y, b = blockIdx.z;
    int m = ob >> 2, h = ob & 3;
    int p = b * NH + h;

    const float* W = (m == 0 ? Wq : m == 1 ? Wk : m == 2 ? Wv : Wskip) + h * 64 * CIN;
    const __nv_bfloat16* Xh = (m == 3 ? g_ph : g_xh) + (size_t)b * CIN * NTOT + nb * 128;
    const __nv_bfloat16* Xl = (m == 3 ? g_pl : g_xl) + (size_t)b * CIN * NTOT + nb * 128;

    // ---- W fp32 -> smem bf16 hi/lo (64 x 128, pitch 272) ----
    #pragma unroll
    for (int l = 0; l < 8; ++l) {
        int idx = tid + l * 256;                   // 2048 float4
        int o = idx >> 5, c4 = (idx & 31) * 4;
        float4 w = *(const float4*)(W + o * 128 + c4);
        __nv_bfloat16 h0, h1, h2, h3, l0, l1, l2, l3;
        split_bf16(w.x, h0, l0); split_bf16(w.y, h1, l1);
        split_bf16(w.z, h2, l2); split_bf16(w.w, h3, l3);
        __nv_bfloat162* dh = (__nv_bfloat162*)(smem + PWH + o * 272 + c4 * 2);
        __nv_bfloat162* dl = (__nv_bfloat162*)(smem + PWL + o * 272 + c4 * 2);
        dh[0] = {h0, h1}; dh[1] = {h2, h3};
        dl[0] = {l0, l1}; dl[1] = {l2, l3};
    }
    // ---- X tiles: 128(c) x 128(n), pitch 272, coalesced uint4 ----
    #pragma unroll
    for (int l = 0; l < 8; ++l) {
        int idx = tid + l * 256;                   // 2048 uint4
        int c = idx >> 4, u = idx & 15;
        *(uint4*)(smem + PXH + c * 272 + u * 16) = ((const uint4*)(Xh + (size_t)c * NTOT))[u];
        *(uint4*)(smem + PXL + c * 272 + u * 16) = ((const uint4*)(Xl + (size_t)c * NTOT))[u];
    }
    __syncthreads();

    int mw = wid & 3, nw = wid >> 2;
    uint32_t wa = sb + PWH + (mw * 16 + (lane & 15)) * 272 + (lane >> 4) * 16;
    uint32_t xb = sb + PXH + (lane & 15) * 272 + (lane >> 4) * 16 + nw * 128;
    float acc[8][4] = {};

    #pragma unroll
    for (int kt = 0; kt < 8; ++kt) {
        uint32_t ah[4], al[4];
        ldsm_x4(ah[0], ah[1], ah[2], ah[3], wa + kt * 32);
        ldsm_x4(al[0], al[1], al[2], al[3], wa + (PWL - PWH) + kt * 32);
        #pragma unroll
        for (int nt = 0; nt < 4; ++nt) {
            uint32_t bh[4], bl[4];
            uint32_t base = xb + kt * 16 * 272 + nt * 32;
            ldsm_x4_t(bh[0], bh[1], bh[2], bh[3], base);
            ldsm_x4_t(bl[0], bl[1], bl[2], bl[3], base + (PXL - PXH));
            mma16816(acc[2 * nt],     ah, bh[0], bh[1]);
            mma16816(acc[2 * nt + 1], ah, bh[2], bh[3]);
            mma16816(acc[2 * nt],     al, bh[0], bh[1]);
            mma16816(acc[2 * nt + 1], al, bh[2], bh[3]);
            mma16816(acc[2 * nt],     ah, bl[0], bl[1]);
            mma16816(acc[2 * nt + 1], ah, bl[2], bl[3]);
        }
    }

    if (m == 3) {                                  // skip -> d_out directly (fp32)
        #pragma unroll
        for (int g = 0; g < 8; ++g) {
            int n_g = nb * 128 + nw * 64 + g * 8 + (lane & 3) * 2;
            #pragma unroll
            for (int cc = 0; cc < 2; ++cc) {
                int o_g = h * 64 + mw * 16 + (lane >> 2) + cc * 8;
                float2 st = {acc[g][2 * cc], acc[g][2 * cc + 1]};
                *(float2*)(out + ((size_t)(b * OUTC + o_g)) * NTOT + n_g) = st;
            }
        }
    } else {                                       // q/k/v -> stage (n,[hi64|lo64]) then copy
        float scale = (m == 0) ? 0.125f : 1.0f;
        __syncthreads();                           // all warps done reading X
        #pragma unroll
        for (int g = 0; g < 8; ++g) {
            int n0 = nw * 64 + g * 8 + (lane & 3) * 2;
            #pragma unroll
            for (int cc = 0; cc < 2; ++cc) {
                int d = mw * 16 + (lane >> 2) + cc * 8;
                #pragma unroll
                for (int e = 0; e < 2; ++e) {
                    int n = n0 + e;
                    __nv_bfloat16 hi, lo;
                    split_bf16(acc[g][2 * cc + e] * scale, hi, lo);
                    *(__nv_bfloat16*)(smem + PXH + n * 272 + d * 2)       = hi;
                    *(__nv_bfloat16*)(smem + PXH + n * 272 + 128 + d * 2) = lo;
                }
            }
        }
        __syncthreads();
        __nv_bfloat16* dst = (m == 0 ? g_q : m == 1 ? g_k : g_v) + ((size_t)p * NTOT + nb * 128) * 128;
        #pragma unroll
        for (int l = 0; l < 8; ++l) {
            int idx = tid + l * 256;               // 2048 uint4 (128 rows x 256 B)
            int n = idx >> 4, u = idx & 15;
            ((uint4*)dst)[idx] = *(const uint4*)(smem + PXH + n * 272 + u * 16);
        }
    }
}

// ============================================================
// K3: fused flash attention, cp.async double-buffered K/V
//     grid (16 it, 16 p), 256 thr = 8 warps x 16 rows
// ============================================================
#define AQ  0
#define AK0 34816
#define AK1 52224
#define AV0 69632
#define AV1 87040
#define SMEM_ATTN 104448

__device__ __forceinline__ void load_kv(uint32_t sb, int p, int c, int s, int tid) {
    const char* gk = (const char*)g_k + ((size_t)p * NTOT + c * 64) * 256;
    const char* gv = (const char*)g_v + ((size_t)p * NTOT + c * 64) * 256;
    uint32_t kd = sb + (s ? AK1 : AK0);
    uint32_t vd = sb + (s ? AV1 : AV0);
    #pragma unroll
    for (int l = 0; l < 4; ++l) {
        int idx = tid + l * 256;                   // 1024 x 16B
        uint32_t off = (idx >> 4) * 272 + (idx & 15) * 16;
        CP16(kd + off, gk + idx * 16);
        CP16(vd + off, gv + idx * 16);
    }
}

__global__ __launch_bounds__(256, 2) void attn_kernel(float* __restrict__ out)
{
    extern __shared__ __align__(1024) char smem[];
    uint32_t sb = smem_u32(smem);
    int tid = threadIdx.x, wid = tid >> 5, lane = tid & 31;
    int it = blockIdx.x, p = blockIdx.y;
    int b = p >> 2, h = p & 3;

    // issue Q + chunk0 as group 0
    {
        const char* gq = (const char*)g_q + ((size_t)p * NTOT + it * 128) * 256;
        #pragma unroll
        for (int l = 0; l < 8; ++l) {
            int idx = tid + l * 256;               // 2048 x 16B
            uint32_t off = (idx >> 4) * 272 + (idx & 15) * 16;
            CP16(sb + AQ + off, gq + idx * 16);
        }
        load_kv(sb, p, 0, 0, tid);
        CP_COMMIT();
    }

    uint32_t qa = sb + AQ + (wid * 16 + (lane & 15)) * 272 + (lane >> 4) * 16;
    uint32_t kb_rel = ((lane & 7) | ((lane & 16) >> 1)) * 272 + ((lane >> 3) & 1) * 16;
    uint32_t vb_rel = (lane & 15) * 272 + (lane >> 4) * 16;

    float o[8][4] = {};
    float rsl = 0.f, rsh = 0.f;

    for (int c = 0; c < NCHUNK; ++c) {
        if (c) __syncthreads();                    // buf[(c+1)&1] free (c-1 MMA done)
        if (c < NCHUNK - 1) {
            load_kv(sb, p, c + 1, (c + 1) & 1, tid);
            CP_COMMIT();
            CP_WAIT(1);                            // chunk c's group complete
        } else {
            CP_WAIT(0);
        }
        __syncthreads();

        uint32_t kb = sb + ((c & 1) ? AK1 : AK0) + kb_rel;
        uint32_t vb = sb + ((c & 1) ? AV1 : AV0) + vb_rel;

        // ---- S = Qh·Kh + Ql·Kh + Qh·Kl ----
        float s[8][4] = {};
        #pragma unroll
        for (int kt = 0; kt < 4; ++kt) {
            uint32_t aqh[4], aql[4];
            ldsm_x4(aqh[0], aqh[1], aqh[2], aqh[3], qa + kt * 32);
            ldsm_x4(aql[0], aql[1], aql[2], aql[3], qa + 128 + kt * 32);
            #pragma unroll
            for (int nt2 = 0; nt2 < 4; ++nt2) {
                uint32_t bh[4], bl[4];
                uint32_t base = kb + nt2 * (16 * 272) + kt * 32;
                ldsm_x4(bh[0], bh[1], bh[2], bh[3], base);
                ldsm_x4(bl[0], bl[1], bl[2], bl[3], base + 128);
                mma16816(s[2 * nt2],     aqh, bh[0], bh[1]);
                mma16816(s[2 * nt2 + 1], aqh, bh[2], bh[3]);
                mma16816(s[2 * nt2],     aql, bh[0], bh[1]);
                mma16816(s[2 * nt2 + 1], aql, bh[2], bh[3]);
                mma16816(s[2 * nt2],     aqh, bl[0], bl[1]);
                mma16816(s[2 * nt2 + 1], aqh, bl[2], bl[3]);
            }
        }

        // ---- exp + bf16 hi/lo pack (A fragments for P·V) ----
        uint32_t ph[4][4], pl[4][4];
        #pragma unroll
        for (int kt = 0; kt < 4; ++kt) {
            #pragma unroll
            for (int hf = 0; hf < 2; ++hf) {
                float* sv = s[2 * kt + hf];
                float e0 = __expf(sv[0]), e1 = __expf(sv[1]);
                float e2 = __expf(sv[2]), e3 = __expf(sv[3]);
                rsl += e0 + e1; rsh += e2 + e3;
                uint32_t h01, h23, l01, l23;
                asm("cvt.rn.bf16x2.f32 %0, %1, %2;" : "=r"(h01) : "f"(e1), "f"(e0));
                asm("cvt.rn.bf16x2.f32 %0, %1, %2;" : "=r"(h23) : "f"(e3), "f"(e2));
                float f0 = __uint_as_float(h01 << 16);
                float f1 = __uint_as_float(h01 & 0xffff0000u);
                float f2 = __uint_as_float(h23 << 16);
                float f3 = __uint_as_float(h23 & 0xffff0000u);
                float r0 = e0 - f0, r1 = e1 - f1, r2 = e2 - f2, r3 = e3 - f3;
                asm("cvt.rn.bf16x2.f32 %0, %1, %2;" : "=r"(l01) : "f"(r1), "f"(r0));
                asm("cvt.rn.bf16x2.f32 %0, %1, %2;" : "=r"(l23) : "f"(r3), "f"(r2));
                ph[kt][2 * hf] = h01; ph[kt][2 * hf + 1] = h23;
                pl[kt][2 * hf] = l01; pl[kt][2 * hf + 1] = l23;
            }
        }

        // ---- O += Ph·Vh + Pl·Vh + Ph·Vl (V via trans-ldmatrix) ----
        #pragma unroll
        for (int kt = 0; kt < 4; ++kt) {
            #pragma unroll
            for (int nt2 = 0; nt2 < 4; ++nt2) {
                uint32_t bh[4], bl[4];
                uint32_t base = vb + kt * (16 * 272) + nt2 * 32;
                ldsm_x4_t(bh[0], bh[1], bh[2], bh[3], base);
                ldsm_x4_t(bl[0], bl[1], bl[2], bl[3], base + 128);
                mma16816(o[2 * nt2],     ph[kt], bh[0], bh[1]);
                mma16816(o[2 * nt2 + 1], ph[kt], bh[2], bh[3]);
                mma16816(o[2 * nt2],     pl[kt], bh[0], bh[1]);
                mma16816(o[2 * nt2 + 1], pl[kt], bh[2], bh[3]);
                mma16816(o[2 * nt2],     ph[kt], bl[0], bl[1]);
                mma16816(o[2 * nt2 + 1], ph[kt], bl[2], bl[3]);
            }
        }
    }

    // ---- normalize + transpose via smem + add to skip ----
    #pragma unroll
    for (int off = 1; off < 4; off <<= 1) {
        rsl += __shfl_xor_sync(0xffffffffu, rsl, off);
        rsh += __shfl_xor_sync(0xffffffffu, rsh, off);
    }
    float invl = 1.0f / rsl, invh = 1.0f / rsh;

    __syncthreads();
    float* Os = (float*)smem;                      // [64][129]
    int i_lo = wid * 16 + (lane >> 2);
    #pragma unroll
    for (int nt = 0; nt < 8; ++nt) {
        int d0 = nt * 8 + (lane & 3) * 2;
        Os[d0 * 129 + i_lo]           = o[nt][0] * invl;
        Os[(d0 + 1) * 129 + i_lo]     = o[nt][1] * invl;
        Os[d0 * 129 + i_lo + 8]       = o[nt][2] * invh;
        Os[(d0 + 1) * 129 + i_lo + 8] = o[nt][3] * invh;
    }
    __syncthreads();

    #pragma unroll
    for (int l = 0; l < 32; ++l) {
        int idx = tid + l * 256;                   // 8192 elements
        int i = idx & 127, d = idx >> 7;
        size_t go = ((size_t)(b * OUTC + h * HD + d)) * NTOT + it * 128 + i;
        out[go] += Os[d * 129 + i];
    }
}

// ============================================================
extern "C" void kernel_launch(void* const* d_in, const int* in_sizes, int n_in,
                              void* d_out, int out_size)
{
    const float* pcd   = (const float*)d_in[0];
    const float* sel   = (const float*)d_in[1];
    const float* drp   = (const float*)d_in[2];
    const int*   isel  = (const int*)d_in[3];
    const int*   idrp  = (const int*)d_in[4];
    const float* Wq    = (const float*)d_in[5];
    const float* Wk    = (const float*)d_in[6];
    const float* Wv    = (const float*)d_in[7];
    const float* Wskip = (const float*)d_in[8];
    float* out = (float*)d_out;

    cudaFuncSetAttribute(proj_kernel, cudaFuncAttributeMaxDynamicSharedMemorySize, SMEM_PROJ);
    cudaFuncSetAttribute(attn_kernel, cudaFuncAttributeMaxDynamicSharedMemorySize, SMEM_ATTN);

    scatter_kernel<<<(NB * CIN * NTOT) / 256, 256>>>(sel, drp, isel, idrp);
    conv_kernel<<<(NB * CIN * NTOT) / 1024, 256>>>(pcd);
    proj_kernel<<<dim3(16, 16, NB), 256, SMEM_PROJ>>>(Wq, Wk, Wv, Wskip, out);
    attn_kernel<<<dim3(16, NP), 256, SMEM_ATTN>>>(out);
}

// round 6
// speedup vs baseline: 4.0192x; 1.0794x over previous
#include <cuda_runtime.h>
#include <cuda_bf16.h>
#include <cstdint>

#define NB   4
#define CIN  128
#define NTOT 2048
#define NH   4
#define HD   64
#define OUTC 256
#define NP   16
#define NCHUNK 32

// ---------------- scratch ----------------
__device__ __nv_bfloat16 g_xh[NB * CIN * NTOT];        // scattered input hi (b,c,n)
__device__ __nv_bfloat16 g_xl[NB * CIN * NTOT];        // scattered input lo
__device__ __nv_bfloat16 g_ph[NB * CIN * NTOT];        // pcd_up hi (b,c,n)
__device__ __nv_bfloat16 g_pl[NB * CIN * NTOT];        // pcd_up lo
__device__ __nv_bfloat16 g_q[NP * NTOT * 128];         // (p,n,[hi64|lo64]) pre-scaled 1/8
__device__ __nv_bfloat16 g_k[NP * NTOT * 128];         // (p,n,[hi64|lo64])
__device__ __nv_bfloat16 g_v[NP * NTOT * 128];         // (p,n,[hi64|lo64])

// ---------------- helpers ----------------
__device__ __forceinline__ uint32_t smem_u32(const void* p) {
    uint32_t a;
    asm("{ .reg .u64 t; cvta.to.shared.u64 t, %1; cvt.u32.u64 %0, t; }" : "=r"(a) : "l"(p));
    return a;
}
__device__ __forceinline__ void ldsm_x4(uint32_t& r0, uint32_t& r1, uint32_t& r2, uint32_t& r3,
                                        uint32_t addr) {
    asm volatile("ldmatrix.sync.aligned.m8n8.x4.shared.b16 {%0,%1,%2,%3}, [%4];"
                 : "=r"(r0), "=r"(r1), "=r"(r2), "=r"(r3) : "r"(addr));
}
__device__ __forceinline__ void ldsm_x4_t(uint32_t& r0, uint32_t& r1, uint32_t& r2, uint32_t& r3,
                                          uint32_t addr) {
    asm volatile("ldmatrix.sync.aligned.m8n8.x4.trans.shared.b16 {%0,%1,%2,%3}, [%4];"
                 : "=r"(r0), "=r"(r1), "=r"(r2), "=r"(r3) : "r"(addr));
}
__device__ __forceinline__ void mma16816(float* d, const uint32_t* a, uint32_t b0, uint32_t b1) {
    asm volatile("mma.sync.aligned.m16n8k16.row.col.f32.bf16.bf16.f32 "
                 "{%0,%1,%2,%3}, {%4,%5,%6,%7}, {%8,%9}, {%0,%1,%2,%3};"
                 : "+f"(d[0]), "+f"(d[1]), "+f"(d[2]), "+f"(d[3])
                 : "r"(a[0]), "r"(a[1]), "r"(a[2]), "r"(a[3]), "r"(b0), "r"(b1));
}
#define CP16(dst, src) asm volatile("cp.async.cg.shared.global [%0], [%1], 16;" :: "r"(dst), "l"(src))
#define CP_COMMIT()    asm volatile("cp.async.commit_group;" ::: "memory")
#define CP_WAIT(n)     asm volatile("cp.async.wait_group %0;" :: "n"(n) : "memory")

__device__ __forceinline__ void split_bf16(float x, __nv_bfloat16& hi, __nv_bfloat16& lo) {
    hi = __float2bfloat16(x);
    lo = __float2bfloat16(x - __bfloat162float(hi));
}

// ============================================================
// K1: scatter concat([select, drop]) -> permuted columns, bf16 hi/lo
// ============================================================
__global__ __launch_bounds__(256) void scatter_kernel(
    const float* __restrict__ sel, const float* __restrict__ drp,
    const int* __restrict__ isel, const int* __restrict__ idrp)
{
    int t  = blockIdx.x * 256 + threadIdx.x;
    int n2 = t & (NTOT - 1);
    int c  = (t >> 11) & (CIN - 1);
    int b  = t >> 18;
    float v; int dst;
    if (n2 < 1024) {
        v   = sel[((size_t)(b * CIN + c)) * 1024 + n2];
        dst = isel[b * 1024 + n2];
    } else {
        int j = n2 - 1024;
        v   = drp[((size_t)(b * CIN + c)) * 1024 + j];
        dst = idrp[b * 1024 + j];
    }
    __nv_bfloat16 hi, lo;
    split_bf16(v, hi, lo);
    size_t off = ((size_t)(b * CIN + c)) * NTOT + dst;
    g_xh[off] = hi;
    g_xl[off] = lo;
}

// ============================================================
// K1b: pcd_up fp32 -> bf16 hi/lo
// ============================================================
__global__ __launch_bounds__(256) void conv_kernel(const float* __restrict__ pcd)
{
    int t = blockIdx.x * 256 + threadIdx.x;        // 262144 float4
    float4 v = ((const float4*)pcd)[t];
    __nv_bfloat16 h0, h1, h2, h3, l0, l1, l2, l3;
    split_bf16(v.x, h0, l0); split_bf16(v.y, h1, l1);
    split_bf16(v.z, h2, l2); split_bf16(v.w, h3, l3);
    __nv_bfloat162* ph = (__nv_bfloat162*)(g_ph + (size_t)t * 4);
    __nv_bfloat162* pl = (__nv_bfloat162*)(g_pl + (size_t)t * 4);
    ph[0] = {h0, h1}; ph[1] = {h2, h3};
    pl[0] = {l0, l1}; pl[1] = {l2, l3};
}

// ============================================================
// K2: projections on tensor cores (3-term bf16 split)
// ============================================================
#define PWH 0
#define PWL 17408
#define PXH 34816
#define PXL 69632
#define SMEM_PROJ 104448

__global__ __launch_bounds__(256, 2) void proj_kernel(
    const float* __restrict__ Wq, const float* __restrict__ Wk,
    const float* __restrict__ Wv, const float* __restrict__ Wskip,
    float* __restrict__ out)
{
    extern __shared__ __align__(1024) char smem[];
    uint32_t sb = smem_u32(smem);
    int tid = threadIdx.x, wid = tid >> 5, lane = tid & 31;
    int nb = blockIdx.x, ob = blockIdx.y, b = blockIdx.z;
    int m = ob >> 2, h = ob & 3;
    int p = b * NH + h;

    const float* W = (m == 0 ? Wq : m == 1 ? Wk : m == 2 ? Wv : Wskip) + h * 64 * CIN;
    const __nv_bfloat16* Xh = (m == 3 ? g_ph : g_xh) + (size_t)b * CIN * NTOT + nb * 128;
    const __nv_bfloat16* Xl = (m == 3 ? g_pl : g_xl) + (size_t)b * CIN * NTOT + nb * 128;

    #pragma unroll
    for (int l = 0; l < 8; ++l) {
        int idx = tid + l * 256;                   // 2048 float4
        int o = idx >> 5, c4 = (idx & 31) * 4;
        float4 w = *(const float4*)(W + o * 128 + c4);
        __nv_bfloat16 h0, h1, h2, h3, l0, l1, l2, l3;
        split_bf16(w.x, h0, l0); split_bf16(w.y, h1, l1);
        split_bf16(w.z, h2, l2); split_bf16(w.w, h3, l3);
        __nv_bfloat162* dh = (__nv_bfloat162*)(smem + PWH + o * 272 + c4 * 2);
        __nv_bfloat162* dl = (__nv_bfloat162*)(smem + PWL + o * 272 + c4 * 2);
        dh[0] = {h0, h1}; dh[1] = {h2, h3};
        dl[0] = {l0, l1}; dl[1] = {l2, l3};
    }
    #pragma unroll
    for (int l = 0; l < 8; ++l) {
        int idx = tid + l * 256;                   // 2048 uint4
        int c = idx >> 4, u = idx & 15;
        *(uint4*)(smem + PXH + c * 272 + u * 16) = ((const uint4*)(Xh + (size_t)c * NTOT))[u];
        *(uint4*)(smem + PXL + c * 272 + u * 16) = ((const uint4*)(Xl + (size_t)c * NTOT))[u];
    }
    __syncthreads();

    int mw = wid & 3, nw = wid >> 2;
    uint32_t wa = sb + PWH + (mw * 16 + (lane & 15)) * 272 + (lane >> 4) * 16;
    uint32_t xb = sb + PXH + (lane & 15) * 272 + (lane >> 4) * 16 + nw * 128;
    float acc[8][4] = {};

    #pragma unroll
    for (int kt = 0; kt < 8; ++kt) {
        uint32_t ah[4], al[4];
        ldsm_x4(ah[0], ah[1], ah[2], ah[3], wa + kt * 32);
        ldsm_x4(al[0], al[1], al[2], al[3], wa + (PWL - PWH) + kt * 32);
        #pragma unroll
        for (int nt = 0; nt < 4; ++nt) {
            uint32_t bh[4], bl[4];
            uint32_t base = xb + kt * 16 * 272 + nt * 32;
            ldsm_x4_t(bh[0], bh[1], bh[2], bh[3], base);
            ldsm_x4_t(bl[0], bl[1], bl[2], bl[3], base + (PXL - PXH));
            mma16816(acc[2 * nt],     ah, bh[0], bh[1]);
            mma16816(acc[2 * nt + 1], ah, bh[2], bh[3]);
            mma16816(acc[2 * nt],     al, bh[0], bh[1]);
            mma16816(acc[2 * nt + 1], al, bh[2], bh[3]);
            mma16816(acc[2 * nt],     ah, bl[0], bl[1]);
            mma16816(acc[2 * nt + 1], ah, bl[2], bl[3]);
        }
    }

    if (m == 3) {
        #pragma unroll
        for (int g = 0; g < 8; ++g) {
            int n_g = nb * 128 + nw * 64 + g * 8 + (lane & 3) * 2;
            #pragma unroll
            for (int cc = 0; cc < 2; ++cc) {
                int o_g = h * 64 + mw * 16 + (lane >> 2) + cc * 8;
                float2 st = {acc[g][2 * cc], acc[g][2 * cc + 1]};
                *(float2*)(out + ((size_t)(b * OUTC + o_g)) * NTOT + n_g) = st;
            }
        }
    } else {
        float scale = (m == 0) ? 0.125f : 1.0f;
        __syncthreads();
        #pragma unroll
        for (int g = 0; g < 8; ++g) {
            int n0 = nw * 64 + g * 8 + (lane & 3) * 2;
            #pragma unroll
            for (int cc = 0; cc < 2; ++cc) {
                int d = mw * 16 + (lane >> 2) + cc * 8;
                #pragma unroll
                for (int e = 0; e < 2; ++e) {
                    int n = n0 + e;
                    __nv_bfloat16 hi, lo;
                    split_bf16(acc[g][2 * cc + e] * scale, hi, lo);
                    *(__nv_bfloat16*)(smem + PXH + n * 272 + d * 2)       = hi;
                    *(__nv_bfloat16*)(smem + PXH + n * 272 + 128 + d * 2) = lo;
                }
            }
        }
        __syncthreads();
        __nv_bfloat16* dst = (m == 0 ? g_q : m == 1 ? g_k : g_v) + ((size_t)p * NTOT + nb * 128) * 128;
        #pragma unroll
        for (int l = 0; l < 8; ++l) {
            int idx = tid + l * 256;               // 2048 uint4
            int n = idx >> 4, u = idx & 15;
            ((uint4*)dst)[idx] = *(const uint4*)(smem + PXH + n * 272 + u * 16);
        }
    }
}

// ============================================================
// K3: fused flash attention; M=32 per warp, i-tile 256, 1 CTA/SM
//     grid (8 it, 16 p), 256 thr = 8 warps
// ============================================================
#define AQ  0
#define AK0 69632
#define AK1 87040
#define AV0 104448
#define AV1 121856
#define SMEM_ATTN 139264

__device__ __forceinline__ void load_kv(uint32_t sb, int p, int c, int s, int tid) {
    const char* gk = (const char*)g_k + ((size_t)p * NTOT + c * 64) * 256;
    const char* gv = (const char*)g_v + ((size_t)p * NTOT + c * 64) * 256;
    uint32_t kd = sb + (s ? AK1 : AK0);
    uint32_t vd = sb + (s ? AV1 : AV0);
    #pragma unroll
    for (int l = 0; l < 4; ++l) {
        int idx = tid + l * 256;                   // 1024 x 16B
        uint32_t off = (idx >> 4) * 272 + (idx & 15) * 16;
        CP16(kd + off, gk + idx * 16);
        CP16(vd + off, gv + idx * 16);
    }
}

__global__ __launch_bounds__(256, 1) void attn_kernel(float* __restrict__ out)
{
    extern __shared__ __align__(1024) char smem[];
    uint32_t sb = smem_u32(smem);
    int tid = threadIdx.x, wid = tid >> 5, lane = tid & 31;
    int it = blockIdx.x, p = blockIdx.y;
    int b = p >> 2, h = p & 3;

    // ---- issue Q (256 rows x 256B) + chunk0 as group 0 ----
    {
        const char* gq = (const char*)g_q + ((size_t)p * NTOT + it * 256) * 256;
        #pragma unroll
        for (int l = 0; l < 16; ++l) {
            int idx = tid + l * 256;               // 4096 x 16B
            uint32_t off = (idx >> 4) * 272 + (idx & 15) * 16;
            CP16(sb + AQ + off, gq + idx * 16);
        }
        load_kv(sb, p, 0, 0, tid);
        CP_COMMIT();
    }

    uint32_t qa = sb + AQ + (wid * 32 + (lane & 15)) * 272 + (lane >> 4) * 16;
    uint32_t kb_rel = ((lane & 7) | ((lane & 16) >> 1)) * 272 + ((lane >> 3) & 1) * 16;
    uint32_t vb_rel = (lane & 15) * 272 + (lane >> 4) * 16;

    float o[2][8][4] = {};
    float rs[2][2] = {};

    for (int c = 0; c < NCHUNK; ++c) {
        if (c) __syncthreads();
        if (c < NCHUNK - 1) {
            load_kv(sb, p, c + 1, (c + 1) & 1, tid);
            CP_COMMIT();
            CP_WAIT(1);
        } else {
            CP_WAIT(0);
        }
        __syncthreads();

        uint32_t kb = sb + ((c & 1) ? AK1 : AK0) + kb_rel;
        uint32_t vb = sb + ((c & 1) ? AV1 : AV0) + vb_rel;

        // ---- S = Qh·Kh + Ql·Kh + Qh·Kl  (32 rows x 64 cols per warp) ----
        float s[2][8][4] = {};
        #pragma unroll
        for (int kt = 0; kt < 4; ++kt) {
            uint32_t aqh[2][4], aql[2][4];
            #pragma unroll
            for (int mi = 0; mi < 2; ++mi) {
                uint32_t qmi = qa + mi * (16 * 272) + kt * 32;
                ldsm_x4(aqh[mi][0], aqh[mi][1], aqh[mi][2], aqh[mi][3], qmi);
                ldsm_x4(aql[mi][0], aql[mi][1], aql[mi][2], aql[mi][3], qmi + 128);
            }
            #pragma unroll
            for (int nt2 = 0; nt2 < 4; ++nt2) {
                uint32_t bh[4], bl[4];
                uint32_t base = kb + nt2 * (16 * 272) + kt * 32;
                ldsm_x4(bh[0], bh[1], bh[2], bh[3], base);
                ldsm_x4(bl[0], bl[1], bl[2], bl[3], base + 128);
                #pragma unroll
                for (int mi = 0; mi < 2; ++mi) {
                    mma16816(s[mi][2 * nt2],     aqh[mi], bh[0], bh[1]);
                    mma16816(s[mi][2 * nt2 + 1], aqh[mi], bh[2], bh[3]);
                    mma16816(s[mi][2 * nt2],     aql[mi], bh[0], bh[1]);
                    mma16816(s[mi][2 * nt2 + 1], aql[mi], bh[2], bh[3]);
                    mma16816(s[mi][2 * nt2],     aqh[mi], bl[0], bl[1]);
                    mma16816(s[mi][2 * nt2 + 1], aqh[mi], bl[2], bl[3]);
                }
            }
        }

        // ---- per-kt: exp+pack (j-group of 16), then P·V for that kt ----
        #pragma unroll
        for (int kt = 0; kt < 4; ++kt) {
            uint32_t ph[2][4], pl[2][4];
            #pragma unroll
            for (int mi = 0; mi < 2; ++mi) {
                #pragma unroll
                for (int hf = 0; hf < 2; ++hf) {
                    float* sv = s[mi][2 * kt + hf];
                    float e0 = __expf(sv[0]), e1 = __expf(sv[1]);
                    float e2 = __expf(sv[2]), e3 = __expf(sv[3]);
                    rs[mi][0] += e0 + e1; rs[mi][1] += e2 + e3;
                    uint32_t h01, h23, l01, l23;
                    asm("cvt.rn.bf16x2.f32 %0, %1, %2;" : "=r"(h01) : "f"(e1), "f"(e0));
                    asm("cvt.rn.bf16x2.f32 %0, %1, %2;" : "=r"(h23) : "f"(e3), "f"(e2));
                    float f0 = __uint_as_float(h01 << 16);
                    float f1 = __uint_as_float(h01 & 0xffff0000u);
                    float f2 = __uint_as_float(h23 << 16);
                    float f3 = __uint_as_float(h23 & 0xffff0000u);
                    float r0 = e0 - f0, r1 = e1 - f1, r2 = e2 - f2, r3 = e3 - f3;
                    asm("cvt.rn.bf16x2.f32 %0, %1, %2;" : "=r"(l01) : "f"(r1), "f"(r0));
                    asm("cvt.rn.bf16x2.f32 %0, %1, %2;" : "=r"(l23) : "f"(r3), "f"(r2));
                    ph[mi][2 * hf] = h01; ph[mi][2 * hf + 1] = h23;
                    pl[mi][2 * hf] = l01; pl[mi][2 * hf + 1] = l23;
                }
            }
            #pragma unroll
            for (int nt2 = 0; nt2 < 4; ++nt2) {
                uint32_t bh[4], bl[4];
                uint32_t base = vb + kt * (16 * 272) + nt2 * 32;
                ldsm_x4_t(bh[0], bh[1], bh[2], bh[3], base);
                ldsm_x4_t(bl[0], bl[1], bl[2], bl[3], base + 128);
                #pragma unroll
                for (int mi = 0; mi < 2; ++mi) {
                    mma16816(o[mi][2 * nt2],     ph[mi], bh[0], bh[1]);
                    mma16816(o[mi][2 * nt2 + 1], ph[mi], bh[2], bh[3]);
                    mma16816(o[mi][2 * nt2],     pl[mi], bh[0], bh[1]);
                    mma16816(o[mi][2 * nt2 + 1], pl[mi], bh[2], bh[3]);
                    mma16816(o[mi][2 * nt2],     ph[mi], bl[0], bl[1]);
                    mma16816(o[mi][2 * nt2 + 1], ph[mi], bl[2], bl[3]);
                }
            }
        }
    }

    // ---- rowsum reduce across quad, normalize, transpose via smem ----
    float inv[2][2];
    #pragma unroll
    for (int mi = 0; mi < 2; ++mi) {
        #pragma unroll
        for (int cc = 0; cc < 2; ++cc) {
            float v = rs[mi][cc];
            v += __shfl_xor_sync(0xffffffffu, v, 1);
            v += __shfl_xor_sync(0xffffffffu, v, 2);
            inv[mi][cc] = 1.0f / v;
        }
    }

    __syncthreads();
    float* Os = (float*)smem;                      // [64][257]
    #pragma unroll
    for (int mi = 0; mi < 2; ++mi) {
        int i0 = wid * 32 + mi * 16 + (lane >> 2);
        #pragma unroll
        for (int nt = 0; nt < 8; ++nt) {
            int d0 = nt * 8 + (lane & 3) * 2;
            Os[d0 * 257 + i0]             = o[mi][nt][0] * inv[mi][0];
            Os[(d0 + 1) * 257 + i0]       = o[mi][nt][1] * inv[mi][0];
            Os[d0 * 257 + i0 + 8]         = o[mi][nt][2] * inv[mi][1];
            Os[(d0 + 1) * 257 + i0 + 8]   = o[mi][nt][3] * inv[mi][1];
        }
    }
    __syncthreads();

    #pragma unroll
    for (int l = 0; l < 64; ++l) {
        int idx = tid + l * 256;                   // 16384 elements
        int i = idx & 255, d = idx >> 8;
        size_t go = ((size_t)(b * OUTC + h * HD + d)) * NTOT + it * 256 + i;
        out[go] += Os[d * 257 + i];
    }
}

// ============================================================
extern "C" void kernel_launch(void* const* d_in, const int* in_sizes, int n_in,
                              void* d_out, int out_size)
{
    const float* pcd   = (const float*)d_in[0];
    const float* sel   = (const float*)d_in[1];
    const float* drp   = (const float*)d_in[2];
    const int*   isel  = (const int*)d_in[3];
    const int*   idrp  = (const int*)d_in[4];
    const float* Wq    = (const float*)d_in[5];
    const float* Wk    = (const float*)d_in[6];
    const float* Wv    = (const float*)d_in[7];
    const float* Wskip = (const float*)d_in[8];
    float* out = (float*)d_out;

    cudaFuncSetAttribute(proj_kernel, cudaFuncAttributeMaxDynamicSharedMemorySize, SMEM_PROJ);
    cudaFuncSetAttribute(attn_kernel, cudaFuncAttributeMaxDynamicSharedMemorySize, SMEM_ATTN);

    scatter_kernel<<<(NB * CIN * NTOT) / 256, 256>>>(sel, drp, isel, idrp);
    conv_kernel<<<(NB * CIN * NTOT) / 1024, 256>>>(pcd);
    proj_kernel<<<dim3(16, 16, NB), 256, SMEM_PROJ>>>(Wq, Wk, Wv, Wskip, out);
    attn_kernel<<<dim3(8, NP), 256, SMEM_ATTN>>>(out);
}

// round 7
// speedup vs baseline: 4.0618x; 1.0106x over previous
#include <cuda_runtime.h>
#include <cuda_bf16.h>
#include <cstdint>

#define NB   4
#define CIN  128
#define NTOT 2048
#define NH   4
#define HD   64
#define OUTC 256
#define NP   16
#define NCHUNK 32

// ---------------- scratch ----------------
__device__ __nv_bfloat16 g_xh[NB * CIN * NTOT];        // scattered input hi (b,c,n)
__device__ __nv_bfloat16 g_xl[NB * CIN * NTOT];        // scattered input lo
__device__ __nv_bfloat16 g_ph[NB * CIN * NTOT];        // pcd_up hi (b,c,n)
__device__ __nv_bfloat16 g_pl[NB * CIN * NTOT];        // pcd_up lo
__device__ __nv_bfloat16 g_q[NP * NTOT * 128];         // (p,n,[hi64|lo64]) pre-scaled 1/8
__device__ __nv_bfloat16 g_k[NP * NTOT * 128];         // (p,n,[hi64|lo64])
__device__ __nv_bfloat16 g_v[NP * NTOT * 128];         // (p,n,[hi64|lo64])

// ---------------- helpers ----------------
__device__ __forceinline__ uint32_t smem_u32(const void* p) {
    uint32_t a;
    asm("{ .reg .u64 t; cvta.to.shared.u64 t, %1; cvt.u32.u64 %0, t; }" : "=r"(a) : "l"(p));
    return a;
}
__device__ __forceinline__ void ldsm_x4(uint32_t& r0, uint32_t& r1, uint32_t& r2, uint32_t& r3,
                                        uint32_t addr) {
    asm volatile("ldmatrix.sync.aligned.m8n8.x4.shared.b16 {%0,%1,%2,%3}, [%4];"
                 : "=r"(r0), "=r"(r1), "=r"(r2), "=r"(r3) : "r"(addr));
}
__device__ __forceinline__ void ldsm_x4_t(uint32_t& r0, uint32_t& r1, uint32_t& r2, uint32_t& r3,
                                          uint32_t addr) {
    asm volatile("ldmatrix.sync.aligned.m8n8.x4.trans.shared.b16 {%0,%1,%2,%3}, [%4];"
                 : "=r"(r0), "=r"(r1), "=r"(r2), "=r"(r3) : "r"(addr));
}
__device__ __forceinline__ void mma16816(float* d, const uint32_t* a, uint32_t b0, uint32_t b1) {
    asm volatile("mma.sync.aligned.m16n8k16.row.col.f32.bf16.bf16.f32 "
                 "{%0,%1,%2,%3}, {%4,%5,%6,%7}, {%8,%9}, {%0,%1,%2,%3};"
                 : "+f"(d[0]), "+f"(d[1]), "+f"(d[2]), "+f"(d[3])
                 : "r"(a[0]), "r"(a[1]), "r"(a[2]), "r"(a[3]), "r"(b0), "r"(b1));
}
#define CP16(dst, src) asm volatile("cp.async.cg.shared.global [%0], [%1], 16;" :: "r"(dst), "l"(src))
#define CP_COMMIT()    asm volatile("cp.async.commit_group;" ::: "memory")
#define CP_WAIT(n)     asm volatile("cp.async.wait_group %0;" :: "n"(n) : "memory")

__device__ __forceinline__ void split_bf16(float x, __nv_bfloat16& hi, __nv_bfloat16& lo) {
    hi = __float2bfloat16(x);
    lo = __float2bfloat16(x - __bfloat162float(hi));
}

// ============================================================
// K1: scatter + pcd convert fused (first half scatter, second conv)
// ============================================================
__global__ __launch_bounds__(256) void prep_kernel(
    const float* __restrict__ sel, const float* __restrict__ drp,
    const int* __restrict__ isel, const int* __restrict__ idrp,
    const float* __restrict__ pcd)
{
    int t = blockIdx.x * 256 + threadIdx.x;
    if (t < (NB * CIN * NTOT)) {                   // scatter: 2^20 scalars
        int n2 = t & (NTOT - 1);
        int c  = (t >> 11) & (CIN - 1);
        int b  = t >> 18;
        float v; int dst;
        if (n2 < 1024) {
            v   = sel[((size_t)(b * CIN + c)) * 1024 + n2];
            dst = isel[b * 1024 + n2];
        } else {
            int j = n2 - 1024;
            v   = drp[((size_t)(b * CIN + c)) * 1024 + j];
            dst = idrp[b * 1024 + j];
        }
        __nv_bfloat16 hi, lo;
        split_bf16(v, hi, lo);
        size_t off = ((size_t)(b * CIN + c)) * NTOT + dst;
        g_xh[off] = hi;
        g_xl[off] = lo;
    } else {                                       // conv: 2^18 float4
        int u = t - NB * CIN * NTOT;
        float4 v = ((const float4*)pcd)[u];
        __nv_bfloat16 h0, h1, h2, h3, l0, l1, l2, l3;
        split_bf16(v.x, h0, l0); split_bf16(v.y, h1, l1);
        split_bf16(v.z, h2, l2); split_bf16(v.w, h3, l3);
        __nv_bfloat162* ph = (__nv_bfloat162*)(g_ph + (size_t)u * 4);
        __nv_bfloat162* pl = (__nv_bfloat162*)(g_pl + (size_t)u * 4);
        ph[0] = {h0, h1}; ph[1] = {h2, h3};
        pl[0] = {l0, l1}; pl[1] = {l2, l3};
    }
}

// ============================================================
// K2: projections on tensor cores (3-term bf16 split)
// ============================================================
#define PWH 0
#define PWL 17408
#define PXH 34816
#define PXL 69632
#define SMEM_PROJ 104448

__global__ __launch_bounds__(256, 2) void proj_kernel(
    const float* __restrict__ Wq, const float* __restrict__ Wk,
    const float* __restrict__ Wv, const float* __restrict__ Wskip,
    float* __restrict__ out)
{
    extern __shared__ __align__(1024) char smem[];
    uint32_t sb = smem_u32(smem);
    int tid = threadIdx.x, wid = tid >> 5, lane = tid & 31;
    int nb = blockIdx.x, ob = blockIdx.y, b = blockIdx.z;
    int m = ob >> 2, h = ob & 3;
    int p = b * NH + h;

    const float* W = (m == 0 ? Wq : m == 1 ? Wk : m == 2 ? Wv : Wskip) + h * 64 * CIN;
    const __nv_bfloat16* Xh = (m == 3 ? g_ph : g_xh) + (size_t)b * CIN * NTOT + nb * 128;
    const __nv_bfloat16* Xl = (m == 3 ? g_pl : g_xl) + (size_t)b * CIN * NTOT + nb * 128;

    #pragma unroll
    for (int l = 0; l < 8; ++l) {
        int idx = tid + l * 256;                   // 2048 float4
        int o = idx >> 5, c4 = (idx & 31) * 4;
        float4 w = *(const float4*)(W + o * 128 + c4);
        __nv_bfloat16 h0, h1, h2, h3, l0, l1, l2, l3;
        split_bf16(w.x, h0, l0); split_bf16(w.y, h1, l1);
        split_bf16(w.z, h2, l2); split_bf16(w.w, h3, l3);
        __nv_bfloat162* dh = (__nv_bfloat162*)(smem + PWH + o * 272 + c4 * 2);
        __nv_bfloat162* dl = (__nv_bfloat162*)(smem + PWL + o * 272 + c4 * 2);
        dh[0] = {h0, h1}; dh[1] = {h2, h3};
        dl[0] = {l0, l1}; dl[1] = {l2, l3};
    }
    #pragma unroll
    for (int l = 0; l < 8; ++l) {
        int idx = tid + l * 256;                   // 2048 uint4
        int c = idx >> 4, u = idx & 15;
        *(uint4*)(smem + PXH + c * 272 + u * 16) = ((const uint4*)(Xh + (size_t)c * NTOT))[u];
        *(uint4*)(smem + PXL + c * 272 + u * 16) = ((const uint4*)(Xl + (size_t)c * NTOT))[u];
    }
    __syncthreads();

    int mw = wid & 3, nw = wid >> 2;
    uint32_t wa = sb + PWH + (mw * 16 + (lane & 15)) * 272 + (lane >> 4) * 16;
    uint32_t xb = sb + PXH + (lane & 15) * 272 + (lane >> 4) * 16 + nw * 128;
    float acc[8][4] = {};

    #pragma unroll
    for (int kt = 0; kt < 8; ++kt) {
        uint32_t ah[4], al[4];
        ldsm_x4(ah[0], ah[1], ah[2], ah[3], wa + kt * 32);
        ldsm_x4(al[0], al[1], al[2], al[3], wa + (PWL - PWH) + kt * 32);
        #pragma unroll
        for (int nt = 0; nt < 4; ++nt) {
            uint32_t bh[4], bl[4];
            uint32_t base = xb + kt * 16 * 272 + nt * 32;
            ldsm_x4_t(bh[0], bh[1], bh[2], bh[3], base);
            ldsm_x4_t(bl[0], bl[1], bl[2], bl[3], base + (PXL - PXH));
            mma16816(acc[2 * nt],     ah, bh[0], bh[1]);
            mma16816(acc[2 * nt + 1], ah, bh[2], bh[3]);
            mma16816(acc[2 * nt],     al, bh[0], bh[1]);
            mma16816(acc[2 * nt + 1], al, bh[2], bh[3]);
            mma16816(acc[2 * nt],     ah, bl[0], bl[1]);
            mma16816(acc[2 * nt + 1], ah, bl[2], bl[3]);
        }
    }

    if (m == 3) {
        #pragma unroll
        for (int g = 0; g < 8; ++g) {
            int n_g = nb * 128 + nw * 64 + g * 8 + (lane & 3) * 2;
            #pragma unroll
            for (int cc = 0; cc < 2; ++cc) {
                int o_g = h * 64 + mw * 16 + (lane >> 2) + cc * 8;
                float2 st = {acc[g][2 * cc], acc[g][2 * cc + 1]};
                *(float2*)(out + ((size_t)(b * OUTC + o_g)) * NTOT + n_g) = st;
            }
        }
    } else {
        float scale = (m == 0) ? 0.125f : 1.0f;
        __syncthreads();
        #pragma unroll
        for (int g = 0; g < 8; ++g) {
            int n0 = nw * 64 + g * 8 + (lane & 3) * 2;
            #pragma unroll
            for (int cc = 0; cc < 2; ++cc) {
                int d = mw * 16 + (lane >> 2) + cc * 8;
                #pragma unroll
                for (int e = 0; e < 2; ++e) {
                    int n = n0 + e;
                    __nv_bfloat16 hi, lo;
                    split_bf16(acc[g][2 * cc + e] * scale, hi, lo);
                    *(__nv_bfloat16*)(smem + PXH + n * 272 + d * 2)       = hi;
                    *(__nv_bfloat16*)(smem + PXH + n * 272 + 128 + d * 2) = lo;
                }
            }
        }
        __syncthreads();
        __nv_bfloat16* dst = (m == 0 ? g_q : m == 1 ? g_k : g_v) + ((size_t)p * NTOT + nb * 128) * 128;
        #pragma unroll
        for (int l = 0; l < 8; ++l) {
            int idx = tid + l * 256;               // 2048 uint4
            int n = idx >> 4, u = idx & 15;
            ((uint4*)dst)[idx] = *(const uint4*)(smem + PXH + n * 272 + u * 16);
        }
    }
}

// ============================================================
// K3: fused flash attention; 4 warps x M=32 = 128 rows/CTA,
//     2 CTAs/SM. grid (16 it, 16 p), 128 threads.
// ============================================================
#define AQ  0
#define AK0 34816
#define AK1 52224
#define AV0 69632
#define AV1 87040
#define SMEM_ATTN 104448

__device__ __forceinline__ void load_kv(uint32_t sb, int p, int c, int s, int tid) {
    const char* gk = (const char*)g_k + ((size_t)p * NTOT + c * 64) * 256;
    const char* gv = (const char*)g_v + ((size_t)p * NTOT + c * 64) * 256;
    uint32_t kd = sb + (s ? AK1 : AK0);
    uint32_t vd = sb + (s ? AV1 : AV0);
    #pragma unroll
    for (int l = 0; l < 8; ++l) {
        int idx = tid + l * 128;                   // 1024 x 16B each
        uint32_t off = (idx >> 4) * 272 + (idx & 15) * 16;
        CP16(kd + off, gk + idx * 16);
        CP16(vd + off, gv + idx * 16);
    }
}

__global__ __launch_bounds__(128, 2) void attn_kernel(float* __restrict__ out)
{
    extern __shared__ __align__(1024) char smem[];
    uint32_t sb = smem_u32(smem);
    int tid = threadIdx.x, wid = tid >> 5, lane = tid & 31;
    int it = blockIdx.x, p = blockIdx.y;
    int b = p >> 2, h = p & 3;

    // ---- issue Q (128 rows x 256B) + chunk0 as group 0 ----
    {
        const char* gq = (const char*)g_q + ((size_t)p * NTOT + it * 128) * 256;
        #pragma unroll
        for (int l = 0; l < 16; ++l) {
            int idx = tid + l * 128;               // 2048 x 16B
            uint32_t off = (idx >> 4) * 272 + (idx & 15) * 16;
            CP16(sb + AQ + off, gq + idx * 16);
        }
        load_kv(sb, p, 0, 0, tid);
        CP_COMMIT();
    }

    uint32_t qa = sb + AQ + (wid * 32 + (lane & 15)) * 272 + (lane >> 4) * 16;
    uint32_t kb_rel = ((lane & 7) | ((lane & 16) >> 1)) * 272 + ((lane >> 3) & 1) * 16;
    uint32_t vb_rel = (lane & 15) * 272 + (lane >> 4) * 16;

    float o[2][8][4] = {};
    float rs[2][2] = {};

    for (int c = 0; c < NCHUNK; ++c) {
        if (c) __syncthreads();
        if (c < NCHUNK - 1) {
            load_kv(sb, p, c + 1, (c + 1) & 1, tid);
            CP_COMMIT();
            CP_WAIT(1);
        } else {
            CP_WAIT(0);
        }
        __syncthreads();

        uint32_t kb = sb + ((c & 1) ? AK1 : AK0) + kb_rel;
        uint32_t vb = sb + ((c & 1) ? AV1 : AV0) + vb_rel;

        // ---- S = Qh·Kh + Ql·Kh + Qh·Kl  (32 rows x 64 cols per warp) ----
        float s[2][8][4] = {};
        #pragma unroll
        for (int kt = 0; kt < 4; ++kt) {
            uint32_t aqh[2][4], aql[2][4];
            #pragma unroll
            for (int mi = 0; mi < 2; ++mi) {
                uint32_t qmi = qa + mi * (16 * 272) + kt * 32;
                ldsm_x4(aqh[mi][0], aqh[mi][1], aqh[mi][2], aqh[mi][3], qmi);
                ldsm_x4(aql[mi][0], aql[mi][1], aql[mi][2], aql[mi][3], qmi + 128);
            }
            #pragma unroll
            for (int nt2 = 0; nt2 < 4; ++nt2) {
                uint32_t bh[4], bl[4];
                uint32_t base = kb + nt2 * (16 * 272) + kt * 32;
                ldsm_x4(bh[0], bh[1], bh[2], bh[3], base);
                ldsm_x4(bl[0], bl[1], bl[2], bl[3], base + 128);
                #pragma unroll
                for (int mi = 0; mi < 2; ++mi) {
                    mma16816(s[mi][2 * nt2],     aqh[mi], bh[0], bh[1]);
                    mma16816(s[mi][2 * nt2 + 1], aqh[mi], bh[2], bh[3]);
                    mma16816(s[mi][2 * nt2],     aql[mi], bh[0], bh[1]);
                    mma16816(s[mi][2 * nt2 + 1], aql[mi], bh[2], bh[3]);
                    mma16816(s[mi][2 * nt2],     aqh[mi], bl[0], bl[1]);
                    mma16816(s[mi][2 * nt2 + 1], aqh[mi], bl[2], bl[3]);
                }
            }
        }

        // ---- per-kt: exp+pack (j-group of 16), then P·V for that kt ----
        #pragma unroll
        for (int kt = 0; kt < 4; ++kt) {
            uint32_t ph[2][4], pl[2][4];
            #pragma unroll
            for (int mi = 0; mi < 2; ++mi) {
                #pragma unroll
                for (int hf = 0; hf < 2; ++hf) {
                    float* sv = s[mi][2 * kt + hf];
                    float e0 = __expf(sv[0]), e1 = __expf(sv[1]);
                    float e2 = __expf(sv[2]), e3 = __expf(sv[3]);
                    rs[mi][0] += e0 + e1; rs[mi][1] += e2 + e3;
                    uint32_t h01, h23, l01, l23;
                    asm("cvt.rn.bf16x2.f32 %0, %1, %2;" : "=r"(h01) : "f"(e1), "f"(e0));
                    asm("cvt.rn.bf16x2.f32 %0, %1, %2;" : "=r"(h23) : "f"(e3), "f"(e2));
                    float f0 = __uint_as_float(h01 << 16);
                    float f1 = __uint_as_float(h01 & 0xffff0000u);
                    float f2 = __uint_as_float(h23 << 16);
                    float f3 = __uint_as_float(h23 & 0xffff0000u);
                    float r0 = e0 - f0, r1 = e1 - f1, r2 = e2 - f2, r3 = e3 - f3;
                    asm("cvt.rn.bf16x2.f32 %0, %1, %2;" : "=r"(l01) : "f"(r1), "f"(r0));
                    asm("cvt.rn.bf16x2.f32 %0, %1, %2;" : "=r"(l23) : "f"(r3), "f"(r2));
                    ph[mi][2 * hf] = h01; ph[mi][2 * hf + 1] = h23;
                    pl[mi][2 * hf] = l01; pl[mi][2 * hf + 1] = l23;
                }
            }
            #pragma unroll
            for (int nt2 = 0; nt2 < 4; ++nt2) {
                uint32_t bh[4], bl[4];
                uint32_t base = vb + kt * (16 * 272) + nt2 * 32;
                ldsm_x4_t(bh[0], bh[1], bh[2], bh[3], base);
                ldsm_x4_t(bl[0], bl[1], bl[2], bl[3], base + 128);
                #pragma unroll
                for (int mi = 0; mi < 2; ++mi) {
                    mma16816(o[mi][2 * nt2],     ph[mi], bh[0], bh[1]);
                    mma16816(o[mi][2 * nt2 + 1], ph[mi], bh[2], bh[3]);
                    mma16816(o[mi][2 * nt2],     pl[mi], bh[0], bh[1]);
                    mma16816(o[mi][2 * nt2 + 1], pl[mi], bh[2], bh[3]);
                    mma16816(o[mi][2 * nt2],     ph[mi], bl[0], bl[1]);
                    mma16816(o[mi][2 * nt2 + 1], ph[mi], bl[2], bl[3]);
                }
            }
        }
    }

    // ---- rowsum reduce across quad, normalize, transpose via smem ----
    float inv[2][2];
    #pragma unroll
    for (int mi = 0; mi < 2; ++mi) {
        #pragma unroll
        for (int cc = 0; cc < 2; ++cc) {
            float v = rs[mi][cc];
            v += __shfl_xor_sync(0xffffffffu, v, 1);
            v += __shfl_xor_sync(0xffffffffu, v, 2);
            inv[mi][cc] = 1.0f / v;
        }
    }

    __syncthreads();
    float* Os = (float*)smem;                      // [64][129]
    #pragma unroll
    for (int mi = 0; mi < 2; ++mi) {
        int i0 = wid * 32 + mi * 16 + (lane >> 2);
        #pragma unroll
        for (int nt = 0; nt < 8; ++nt) {
            int d0 = nt * 8 + (lane & 3) * 2;
            Os[d0 * 129 + i0]           = o[mi][nt][0] * inv[mi][0];
            Os[(d0 + 1) * 129 + i0]     = o[mi][nt][1] * inv[mi][0];
            Os[d0 * 129 + i0 + 8]       = o[mi][nt][2] * inv[mi][1];
            Os[(d0 + 1) * 129 + i0 + 8] = o[mi][nt][3] * inv[mi][1];
        }
    }
    __syncthreads();

    #pragma unroll
    for (int l = 0; l < 64; ++l) {
        int idx = tid + l * 128;                   // 8192 elements
        int i = idx & 127, d = idx >> 7;
        size_t go = ((size_t)(b * OUTC + h * HD + d)) * NTOT + it * 128 + i;
        out[go] += Os[d * 129 + i];
    }
}

// ============================================================
extern "C" void kernel_launch(void* const* d_in, const int* in_sizes, int n_in,
                              void* d_out, int out_size)
{
    const float* pcd   = (const float*)d_in[0];
    const float* sel   = (const float*)d_in[1];
    const float* drp   = (const float*)d_in[2];
    const int*   isel  = (const int*)d_in[3];
    const int*   idrp  = (const int*)d_in[4];
    const float* Wq    = (const float*)d_in[5];
    const float* Wk    = (const float*)d_in[6];
    const float* Wv    = (const float*)d_in[7];
    const float* Wskip = (const float*)d_in[8];
    float* out = (float*)d_out;

    cudaFuncSetAttribute(proj_kernel, cudaFuncAttributeMaxDynamicSharedMemorySize, SMEM_PROJ);
    cudaFuncSetAttribute(attn_kernel, cudaFuncAttributeMaxDynamicSharedMemorySize, SMEM_ATTN);

    int prep_total = NB * CIN * NTOT + NB * CIN * NTOT / 4;   // scatter + conv lanes
    prep_kernel<<<(prep_total + 255) / 256, 256>>>(sel, drp, isel, idrp, pcd);
    proj_kernel<<<dim3(16, 16, NB), 256, SMEM_PROJ>>>(Wq, Wk, Wv, Wskip, out);
    attn_kernel<<<dim3(16, NP), 128, SMEM_ATTN>>>(out);
}

// round 8
// speedup vs baseline: 4.4489x; 1.0953x over previous
#include <cuda_runtime.h>
#include <cuda_bf16.h>
#include <cstdint>

#define NB   4
#define CIN  128
#define NTOT 2048
#define NH   4
#define HD   64
#define OUTC 256
#define NP   16
#define NCHUNK 32

// ---------------- scratch ----------------
__device__ __nv_bfloat16 g_xh[NB * CIN * NTOT];        // scattered input hi (b,c,n)
__device__ __nv_bfloat16 g_xl[NB * CIN * NTOT];        // scattered input lo
__device__ __nv_bfloat16 g_ph[NB * CIN * NTOT];        // pcd_up hi (b,c,n)
__device__ __nv_bfloat16 g_pl[NB * CIN * NTOT];        // pcd_up lo
__device__ float g_q[NP * NTOT * HD];                  // (p,n,d) tf32-rounded, pre-scaled 1/8
__device__ float g_k[NP * NTOT * HD];                  // (p,n,d) tf32-rounded
__device__ float g_v[NP * HD * NTOT];                  // (p,d,n) tf32-rounded

// ---------------- helpers ----------------
__device__ __forceinline__ uint32_t smem_u32(const void* p) {
    uint32_t a;
    asm("{ .reg .u64 t; cvta.to.shared.u64 t, %1; cvt.u32.u64 %0, t; }" : "=r"(a) : "l"(p));
    return a;
}
__device__ __forceinline__ void ldsm_x4(uint32_t& r0, uint32_t& r1, uint32_t& r2, uint32_t& r3,
                                        uint32_t addr) {
    asm volatile("ldmatrix.sync.aligned.m8n8.x4.shared.b16 {%0,%1,%2,%3}, [%4];"
                 : "=r"(r0), "=r"(r1), "=r"(r2), "=r"(r3) : "r"(addr));
}
__device__ __forceinline__ void ldsm_x4_t(uint32_t& r0, uint32_t& r1, uint32_t& r2, uint32_t& r3,
                                          uint32_t addr) {
    asm volatile("ldmatrix.sync.aligned.m8n8.x4.trans.shared.b16 {%0,%1,%2,%3}, [%4];"
                 : "=r"(r0), "=r"(r1), "=r"(r2), "=r"(r3) : "r"(addr));
}
__device__ __forceinline__ void mma16816(float* d, const uint32_t* a, uint32_t b0, uint32_t b1) {
    asm volatile("mma.sync.aligned.m16n8k16.row.col.f32.bf16.bf16.f32 "
                 "{%0,%1,%2,%3}, {%4,%5,%6,%7}, {%8,%9}, {%0,%1,%2,%3};"
                 : "+f"(d[0]), "+f"(d[1]), "+f"(d[2]), "+f"(d[3])
                 : "r"(a[0]), "r"(a[1]), "r"(a[2]), "r"(a[3]), "r"(b0), "r"(b1));
}
__device__ __forceinline__ void mma1688(float* d, const float* a, float b0, float b1) {
    asm volatile("mma.sync.aligned.m16n8k8.row.col.f32.tf32.tf32.f32 "
                 "{%0,%1,%2,%3}, {%4,%5,%6,%7}, {%8,%9}, {%0,%1,%2,%3};"
                 : "+f"(d[0]), "+f"(d[1]), "+f"(d[2]), "+f"(d[3])
                 : "r"(__float_as_uint(a[0])), "r"(__float_as_uint(a[1])),
                   "r"(__float_as_uint(a[2])), "r"(__float_as_uint(a[3])),
                   "r"(__float_as_uint(b0)), "r"(__float_as_uint(b1)));
}
__device__ __forceinline__ float tf32r(float x) {
    uint32_t u;
    asm("cvt.rna.tf32.f32 %0, %1;" : "=r"(u) : "f"(x));
    return __uint_as_float(u);
}
#define CP16(dst, src) asm volatile("cp.async.cg.shared.global [%0], [%1], 16;" :: "r"(dst), "l"(src))
#define CP_COMMIT()    asm volatile("cp.async.commit_group;" ::: "memory")
#define CP_WAIT(n)     asm volatile("cp.async.wait_group %0;" :: "n"(n) : "memory")

__device__ __forceinline__ void split_bf16(float x, __nv_bfloat16& hi, __nv_bfloat16& lo) {
    hi = __float2bfloat16(x);
    lo = __float2bfloat16(x - __bfloat162float(hi));
}

// ============================================================
// K1: scatter + pcd convert fused
// ============================================================
__global__ __launch_bounds__(256) void prep_kernel(
    const float* __restrict__ sel, const float* __restrict__ drp,
    const int* __restrict__ isel, const int* __restrict__ idrp,
    const float* __restrict__ pcd)
{
    int t = blockIdx.x * 256 + threadIdx.x;
    if (t < (NB * CIN * NTOT)) {
        int n2 = t & (NTOT - 1);
        int c  = (t >> 11) & (CIN - 1);
        int b  = t >> 18;
        float v; int dst;
        if (n2 < 1024) {
            v   = sel[((size_t)(b * CIN + c)) * 1024 + n2];
            dst = isel[b * 1024 + n2];
        } else {
            int j = n2 - 1024;
            v   = drp[((size_t)(b * CIN + c)) * 1024 + j];
            dst = idrp[b * 1024 + j];
        }
        __nv_bfloat16 hi, lo;
        split_bf16(v, hi, lo);
        size_t off = ((size_t)(b * CIN + c)) * NTOT + dst;
        g_xh[off] = hi;
        g_xl[off] = lo;
    } else {
        int u = t - NB * CIN * NTOT;
        float4 v = ((const float4*)pcd)[u];
        __nv_bfloat16 h0, h1, h2, h3, l0, l1, l2, l3;
        split_bf16(v.x, h0, l0); split_bf16(v.y, h1, l1);
        split_bf16(v.z, h2, l2); split_bf16(v.w, h3, l3);
        __nv_bfloat162* ph = (__nv_bfloat162*)(g_ph + (size_t)u * 4);
        __nv_bfloat162* pl = (__nv_bfloat162*)(g_pl + (size_t)u * 4);
        ph[0] = {h0, h1}; ph[1] = {h2, h3};
        pl[0] = {l0, l1}; pl[1] = {l2, l3};
    }
}

// ============================================================
// K2: projections on tensor cores (3-term bf16 split inputs),
//     outputs: skip fp32 -> d_out; q/k fp32 tf32-rounded (p,n,d);
//     v fp32 tf32-rounded (p,d,n)
// ============================================================
#define PWH 0
#define PWL 17408
#define PXH 34816
#define PXL 69632
#define SMEM_PROJ 104448

__global__ __launch_bounds__(256, 2) void proj_kernel(
    const float* __restrict__ Wq, const float* __restrict__ Wk,
    const float* __restrict__ Wv, const float* __restrict__ Wskip,
    float* __restrict__ out)
{
    extern __shared__ __align__(1024) char smem[];
    uint32_t sb = smem_u32(smem);
    int tid = threadIdx.x, wid = tid >> 5, lane = tid & 31;
    int nb = blockIdx.x, ob = blockIdx.y, b = blockIdx.z;
    int m = ob >> 2, h = ob & 3;
    int p = b * NH + h;

    const float* W = (m == 0 ? Wq : m == 1 ? Wk : m == 2 ? Wv : Wskip) + h * 64 * CIN;
    const __nv_bfloat16* Xh = (m == 3 ? g_ph : g_xh) + (size_t)b * CIN * NTOT + nb * 128;
    const __nv_bfloat16* Xl = (m == 3 ? g_pl : g_xl) + (size_t)b * CIN * NTOT + nb * 128;

    #pragma unroll
    for (int l = 0; l < 8; ++l) {
        int idx = tid + l * 256;                   // 2048 float4
        int o = idx >> 5, c4 = (idx & 31) * 4;
        float4 w = *(const float4*)(W + o * 128 + c4);
        __nv_bfloat16 h0, h1, h2, h3, l0, l1, l2, l3;
        split_bf16(w.x, h0, l0); split_bf16(w.y, h1, l1);
        split_bf16(w.z, h2, l2); split_bf16(w.w, h3, l3);
        __nv_bfloat162* dh = (__nv_bfloat162*)(smem + PWH + o * 272 + c4 * 2);
        __nv_bfloat162* dl = (__nv_bfloat162*)(smem + PWL + o * 272 + c4 * 2);
        dh[0] = {h0, h1}; dh[1] = {h2, h3};
        dl[0] = {l0, l1}; dl[1] = {l2, l3};
    }
    #pragma unroll
    for (int l = 0; l < 8; ++l) {
        int idx = tid + l * 256;                   // 2048 uint4
        int c = idx >> 4, u = idx & 15;
        *(uint4*)(smem + PXH + c * 272 + u * 16) = ((const uint4*)(Xh + (size_t)c * NTOT))[u];
        *(uint4*)(smem + PXL + c * 272 + u * 16) = ((const uint4*)(Xl + (size_t)c * NTOT))[u];
    }
    __syncthreads();

    int mw = wid & 3, nw = wid >> 2;
    uint32_t wa = sb + PWH + (mw * 16 + (lane & 15)) * 272 + (lane >> 4) * 16;
    uint32_t xb = sb + PXH + (lane & 15) * 272 + (lane >> 4) * 16 + nw * 128;
    float acc[8][4] = {};

    #pragma unroll
    for (int kt = 0; kt < 8; ++kt) {
        uint32_t ah[4], al[4];
        ldsm_x4(ah[0], ah[1], ah[2], ah[3], wa + kt * 32);
        ldsm_x4(al[0], al[1], al[2], al[3], wa + (PWL - PWH) + kt * 32);
        #pragma unroll
        for (int nt = 0; nt < 4; ++nt) {
            uint32_t bh[4], bl[4];
            uint32_t base = xb + kt * 16 * 272 + nt * 32;
            ldsm_x4_t(bh[0], bh[1], bh[2], bh[3], base);
            ldsm_x4_t(bl[0], bl[1], bl[2], bl[3], base + (PXL - PXH));
            mma16816(acc[2 * nt],     ah, bh[0], bh[1]);
            mma16816(acc[2 * nt + 1], ah, bh[2], bh[3]);
            mma16816(acc[2 * nt],     al, bh[0], bh[1]);
            mma16816(acc[2 * nt + 1], al, bh[2], bh[3]);
            mma16816(acc[2 * nt],     ah, bl[0], bl[1]);
            mma16816(acc[2 * nt + 1], ah, bl[2], bl[3]);
        }
    }

    if (m == 3) {                                  // skip -> d_out (fp32, exact)
        #pragma unroll
        for (int g = 0; g < 8; ++g) {
            int n_g = nb * 128 + nw * 64 + g * 8 + (lane & 3) * 2;
            #pragma unroll
            for (int cc = 0; cc < 2; ++cc) {
                int o_g = h * 64 + mw * 16 + (lane >> 2) + cc * 8;
                float2 st = {acc[g][2 * cc], acc[g][2 * cc + 1]};
                *(float2*)(out + ((size_t)(b * OUTC + o_g)) * NTOT + n_g) = st;
            }
        }
    } else if (m == 2) {                           // v: stage [d][n] pitch 132, -> (p,d,n)
        __syncthreads();
        float* S = (float*)smem;
        #pragma unroll
        for (int g = 0; g < 8; ++g) {
            int n0 = nw * 64 + g * 8 + (lane & 3) * 2;
            #pragma unroll
            for (int cc = 0; cc < 2; ++cc) {
                int d = mw * 16 + (lane >> 2) + cc * 8;
                #pragma unroll
                for (int e = 0; e < 2; ++e)
                    S[d * 132 + n0 + e] = tf32r(acc[g][2 * cc + e]);
            }
        }
        __syncthreads();
        float* dst = g_v + (size_t)p * HD * NTOT + nb * 128;
        #pragma unroll
        for (int l = 0; l < 8; ++l) {
            int idx = tid + l * 256;               // 2048 float4: 64 d x 32
            int d = idx >> 5, u = idx & 31;
            *(float4*)(dst + (size_t)d * NTOT + u * 4) = *(float4*)&S[d * 132 + u * 4];
        }
    } else {                                       // q/k: stage [n][d] pitch 68, -> (p,n,d)
        float scale = (m == 0) ? 0.125f : 1.0f;
        __syncthreads();
        float* S = (float*)smem;
        #pragma unroll
        for (int g = 0; g < 8; ++g) {
            int n0 = nw * 64 + g * 8 + (lane & 3) * 2;
            #pragma unroll
            for (int cc = 0; cc < 2; ++cc) {
                int d = mw * 16 + (lane >> 2) + cc * 8;
                #pragma unroll
                for (int e = 0; e < 2; ++e)
                    S[(n0 + e) * 68 + d] = tf32r(acc[g][2 * cc + e] * scale);
            }
        }
        __syncthreads();
        float* dst = (m == 0 ? g_q : g_k) + ((size_t)p * NTOT + nb * 128) * HD;
        #pragma unroll
        for (int l = 0; l < 8; ++l) {
            int idx = tid + l * 256;               // 2048 float4: 128 n x 16
            int n = idx >> 4, u = idx & 15;
            *(float4*)(dst + n * HD + u * 4) = *(float4*)&S[n * 68 + u * 4];
        }
    }
}

// ============================================================
// K3: fused flash attention, single-term tf32 mma
//     4 warps x M=32 = 128 rows/CTA, 2 CTAs/SM, grid (16 it, 16 p)
// ============================================================
#define AQ  0
#define AK0 34816
#define AK1 52224
#define AV0 69632
#define AV1 87040
#define SMEM_ATTN 104448

__device__ __forceinline__ void load_kv(uint32_t sb, int p, int c, int s, int tid) {
    const char* gk = (const char*)(g_k + ((size_t)p * NTOT + c * 64) * HD);
    const char* gv = (const char*)(g_v + (size_t)p * HD * NTOT + c * 64);
    uint32_t kd = sb + (s ? AK1 : AK0);
    uint32_t vd = sb + (s ? AV1 : AV0);
    #pragma unroll
    for (int l = 0; l < 8; ++l) {
        int idx = tid + l * 128;                   // 1024 x 16B each
        int row = idx >> 4, c16 = (idx & 15) * 16;
        CP16(kd + row * 272 + c16, gk + (size_t)row * (HD * 4) + c16);
        CP16(vd + row * 272 + c16, gv + (size_t)row * (NTOT * 4) + c16);
    }
}

__global__ __launch_bounds__(128, 2) void attn_kernel(float* __restrict__ out)
{
    extern __shared__ __align__(1024) char smem[];
    uint32_t sb = smem_u32(smem);
    int tid = threadIdx.x, wid = tid >> 5, lane = tid & 31;
    int g = lane >> 2, t = lane & 3;
    int it = blockIdx.x, p = blockIdx.y;
    int b = p >> 2, h = p & 3;

    // ---- issue Q (128 rows x 256B fp32) + chunk0 as group 0 ----
    {
        const char* gq = (const char*)(g_q + ((size_t)p * NTOT + it * 128) * HD);
        #pragma unroll
        for (int l = 0; l < 16; ++l) {
            int idx = tid + l * 128;               // 2048 x 16B
            int row = idx >> 4, c16 = (idx & 15) * 16;
            CP16(sb + AQ + row * 272 + c16, gq + (size_t)row * (HD * 4) + c16);
        }
        load_kv(sb, p, 0, 0, tid);
        CP_COMMIT();
    }

    int src0 = (lane & ~3) | ((lane >> 1) & 1);    // (t>>1) within quad
    int src1 = src0 + 2;
    bool oddt = lane & 1;

    float o[2][8][4] = {};
    float rs[2][2] = {};

    for (int c = 0; c < NCHUNK; ++c) {
        if (c) __syncthreads();
        if (c < NCHUNK - 1) {
            load_kv(sb, p, c + 1, (c + 1) & 1, tid);
            CP_COMMIT();
            CP_WAIT(1);
        } else {
            CP_WAIT(0);
        }
        __syncthreads();

        const char* kbp = smem + ((c & 1) ? AK1 : AK0);
        const char* vbp = smem + ((c & 1) ? AV1 : AV0);

        // ---- S = Q Kᵀ, tf32 single term: 8 k-steps x (2 mi x 8 jt) ----
        float s[2][8][4] = {};
        #pragma unroll
        for (int ks = 0; ks < 8; ++ks) {
            float a[2][4];
            #pragma unroll
            for (int mi = 0; mi < 2; ++mi) {
                const char* ra = smem + AQ + (wid * 32 + mi * 16 + g) * 272 + (ks * 8 + t) * 4;
                a[mi][0] = *(const float*)(ra);
                a[mi][1] = *(const float*)(ra + 8 * 272);
                a[mi][2] = *(const float*)(ra + 16);
                a[mi][3] = *(const float*)(ra + 8 * 272 + 16);
            }
            #pragma unroll
            for (int jt = 0; jt < 8; ++jt) {
                const char* rb = kbp + (jt * 8 + g) * 272 + (ks * 8 + t) * 4;
                float b0 = *(const float*)(rb);
                float b1 = *(const float*)(rb + 16);
                mma1688(s[0][jt], a[0], b0, b1);
                mma1688(s[1][jt], a[1], b0, b1);
            }
        }

        // ---- exp + tf32 round + rowsum (post-round values used everywhere) ----
        #pragma unroll
        for (int mi = 0; mi < 2; ++mi) {
            #pragma unroll
            for (int jt = 0; jt < 8; ++jt) {
                float p0 = tf32r(__expf(s[mi][jt][0]));
                float p1 = tf32r(__expf(s[mi][jt][1]));
                float p2 = tf32r(__expf(s[mi][jt][2]));
                float p3 = tf32r(__expf(s[mi][jt][3]));
                rs[mi][0] += p0 + p1;
                rs[mi][1] += p2 + p3;
                s[mi][jt][0] = p0; s[mi][jt][1] = p1;
                s[mi][jt][2] = p2; s[mi][jt][3] = p3;
            }
        }

        // ---- O += P V : per k-step (j-group of 8) shuffle P c-frag -> A-frag ----
        #pragma unroll
        for (int ks = 0; ks < 8; ++ks) {
            float a[2][4];
            #pragma unroll
            for (int mi = 0; mi < 2; ++mi) {
                float p0 = s[mi][ks][0], p1 = s[mi][ks][1];
                float p2 = s[mi][ks][2], p3 = s[mi][ks][3];
                float v00 = __shfl_sync(0xffffffffu, p0, src0);
                float v01 = __shfl_sync(0xffffffffu, p1, src0);
                float v10 = __shfl_sync(0xffffffffu, p2, src0);
                float v11 = __shfl_sync(0xffffffffu, p3, src0);
                float v20 = __shfl_sync(0xffffffffu, p0, src1);
                float v21 = __shfl_sync(0xffffffffu, p1, src1);
                float v30 = __shfl_sync(0xffffffffu, p2, src1);
                float v31 = __shfl_sync(0xffffffffu, p3, src1);
                a[mi][0] = oddt ? v01 : v00;
                a[mi][1] = oddt ? v11 : v10;
                a[mi][2] = oddt ? v21 : v20;
                a[mi][3] = oddt ? v31 : v30;
            }
            #pragma unroll
            for (int dt = 0; dt < 8; ++dt) {
                const char* rb = vbp + (dt * 8 + g) * 272 + (ks * 8 + t) * 4;
                float b0 = *(const float*)(rb);
                float b1 = *(const float*)(rb + 16);
                mma1688(o[0][dt], a[0], b0, b1);
                mma1688(o[1][dt], a[1], b0, b1);
            }
        }
    }

    // ---- rowsum reduce across quad, normalize, transpose via smem ----
    float inv[2][2];
    #pragma unroll
    for (int mi = 0; mi < 2; ++mi) {
        #pragma unroll
        for (int cc = 0; cc < 2; ++cc) {
            float v = rs[mi][cc];
            v += __shfl_xor_sync(0xffffffffu, v, 1);
            v += __shfl_xor_sync(0xffffffffu, v, 2);
            inv[mi][cc] = 1.0f / v;
        }
    }

    __syncthreads();
    float* Os = (float*)smem;                      // [64][129]
    #pragma unroll
    for (int mi = 0; mi < 2; ++mi) {
        int i0 = wid * 32 + mi * 16 + g;
        #pragma unroll
        for (int dt = 0; dt < 8; ++dt) {
            int d0 = dt * 8 + t * 2;
            Os[d0 * 129 + i0]           = o[mi][dt][0] * inv[mi][0];
            Os[(d0 + 1) * 129 + i0]     = o[mi][dt][1] * inv[mi][0];
            Os[d0 * 129 + i0 + 8]       = o[mi][dt][2] * inv[mi][1];
            Os[(d0 + 1) * 129 + i0 + 8] = o[mi][dt][3] * inv[mi][1];
        }
    }
    __syncthreads();

    #pragma unroll
    for (int l = 0; l < 64; ++l) {
        int idx = tid + l * 128;                   // 8192 elements
        int i = idx & 127, d = idx >> 7;
        size_t go = ((size_t)(b * OUTC + h * HD + d)) * NTOT + it * 128 + i;
        out[go] += Os[d * 129 + i];
    }
}

// ============================================================
extern "C" void kernel_launch(void* const* d_in, const int* in_sizes, int n_in,
                              void* d_out, int out_size)
{
    const float* pcd   = (const float*)d_in[0];
    const float* sel   = (const float*)d_in[1];
    const float* drp   = (const float*)d_in[2];
    const int*   isel  = (const int*)d_in[3];
    const int*   idrp  = (const int*)d_in[4];
    const float* Wq    = (const float*)d_in[5];
    const float* Wk    = (const float*)d_in[6];
    const float* Wv    = (const float*)d_in[7];
    const float* Wskip = (const float*)d_in[8];
    float* out = (float*)d_out;

    cudaFuncSetAttribute(proj_kernel, cudaFuncAttributeMaxDynamicSharedMemorySize, SMEM_PROJ);
    cudaFuncSetAttribute(attn_kernel, cudaFuncAttributeMaxDynamicSharedMemorySize, SMEM_ATTN);

    int prep_total = NB * CIN * NTOT + NB * CIN * NTOT / 4;
    prep_kernel<<<(prep_total + 255) / 256, 256>>>(sel, drp, isel, idrp, pcd);
    proj_kernel<<<dim3(16, 16, NB), 256, SMEM_PROJ>>>(Wq, Wk, Wv, Wskip, out);
    attn_kernel<<<dim3(16, NP), 128, SMEM_ATTN>>>(out);
}

// round 9
// speedup vs baseline: 4.9122x; 1.1041x over previous
#include <cuda_runtime.h>
#include <cuda_bf16.h>
#include <cstdint>

#define NB   4
#define CIN  128
#define NTOT 2048
#define NH   4
#define HD   64
#define OUTC 256
#define NP   16
#define NCHUNK 32

// ---------------- scratch ----------------
__device__ __nv_bfloat16 g_xh[NB * NTOT * CIN];        // scattered input hi (b,n,c)
__device__ __nv_bfloat16 g_xl[NB * NTOT * CIN];        // scattered input lo
__device__ __nv_bfloat16 g_ph[NB * NTOT * CIN];        // pcd_up hi (b,n,c)
__device__ __nv_bfloat16 g_pl[NB * NTOT * CIN];        // pcd_up lo
__device__ float g_q[NP * NTOT * HD];                  // (p,n,d') tf32, pre-scaled 1/8, d interleaved
__device__ float g_k[NP * NTOT * HD];                  // (p,n,d') tf32, d interleaved
__device__ float g_v[NP * HD * NTOT];                  // (p,d,n) tf32, natural

// ---------------- helpers ----------------
__device__ __forceinline__ uint32_t smem_u32(const void* p) {
    uint32_t a;
    asm("{ .reg .u64 t; cvta.to.shared.u64 t, %1; cvt.u32.u64 %0, t; }" : "=r"(a) : "l"(p));
    return a;
}
__device__ __forceinline__ void ldsm_x4(uint32_t& r0, uint32_t& r1, uint32_t& r2, uint32_t& r3,
                                        uint32_t addr) {
    asm volatile("ldmatrix.sync.aligned.m8n8.x4.shared.b16 {%0,%1,%2,%3}, [%4];"
                 : "=r"(r0), "=r"(r1), "=r"(r2), "=r"(r3) : "r"(addr));
}
__device__ __forceinline__ void mma16816(float* d, const uint32_t* a, uint32_t b0, uint32_t b1) {
    asm volatile("mma.sync.aligned.m16n8k16.row.col.f32.bf16.bf16.f32 "
                 "{%0,%1,%2,%3}, {%4,%5,%6,%7}, {%8,%9}, {%0,%1,%2,%3};"
                 : "+f"(d[0]), "+f"(d[1]), "+f"(d[2]), "+f"(d[3])
                 : "r"(a[0]), "r"(a[1]), "r"(a[2]), "r"(a[3]), "r"(b0), "r"(b1));
}
__device__ __forceinline__ void mma1688(float* d, float a0, float a1, float a2, float a3,
                                        float b0, float b1) {
    asm volatile("mma.sync.aligned.m16n8k8.row.col.f32.tf32.tf32.f32 "
                 "{%0,%1,%2,%3}, {%4,%5,%6,%7}, {%8,%9}, {%0,%1,%2,%3};"
                 : "+f"(d[0]), "+f"(d[1]), "+f"(d[2]), "+f"(d[3])
                 : "r"(__float_as_uint(a0)), "r"(__float_as_uint(a1)),
                   "r"(__float_as_uint(a2)), "r"(__float_as_uint(a3)),
                   "r"(__float_as_uint(b0)), "r"(__float_as_uint(b1)));
}
__device__ __forceinline__ float tf32r(float x) {
    uint32_t u;
    asm("cvt.rna.tf32.f32 %0, %1;" : "=r"(u) : "f"(x));
    return __uint_as_float(u);
}
#define CP16(dst, src) asm volatile("cp.async.cg.shared.global [%0], [%1], 16;" :: "r"(dst), "l"(src))
#define CP_COMMIT()    asm volatile("cp.async.commit_group;" ::: "memory")
#define CP_WAIT(n)     asm volatile("cp.async.wait_group %0;" :: "n"(n) : "memory")

__device__ __forceinline__ void split_bf16(float x, __nv_bfloat16& hi, __nv_bfloat16& lo) {
    hi = __float2bfloat16(x);
    lo = __float2bfloat16(x - __bfloat162float(hi));
}

// ============================================================
// K1: tiled transpose + scatter -> (b,n,c) bf16 hi/lo
//     grid (64 n-tiles, 2 modes, 4 b), 256 thr
// ============================================================
__global__ __launch_bounds__(256) void prep_kernel(
    const float* __restrict__ sel, const float* __restrict__ drp,
    const int* __restrict__ isel, const int* __restrict__ idrp,
    const float* __restrict__ pcd)
{
    __shared__ float S[128][33];
    __shared__ int dsts[32];
    int tx = blockIdx.x, mode = blockIdx.y, b = blockIdx.z;
    int t = threadIdx.x;

    if (mode == 0) {
        const float* src; const int* ip; int n0;
        if (tx < 32) { src = sel + (size_t)b * CIN * 1024; ip = isel; n0 = tx * 32; }
        else         { src = drp + (size_t)b * CIN * 1024; ip = idrp; n0 = tx * 32 - 1024; }
        #pragma unroll
        for (int i = 0; i < 16; ++i) {
            int idx = t + i * 256;
            int c = idx >> 5, n = idx & 31;
            S[c][n] = src[(size_t)c * 1024 + n0 + n];
        }
        if (t < 32) dsts[t] = ip[b * 1024 + n0 + t];
    } else {
        int n0 = tx * 32;
        #pragma unroll
        for (int i = 0; i < 16; ++i) {
            int idx = t + i * 256;
            int c = idx >> 5, n = idx & 31;
            S[c][n] = pcd[((size_t)b * CIN + c) * NTOT + n0 + n];
        }
        if (t < 32) dsts[t] = n0 + t;
    }
    __syncthreads();

    int n = t >> 3, cs = (t & 7) * 16;
    int dst = dsts[n];
    __nv_bfloat16* dh = (mode == 0 ? g_xh : g_ph) + ((size_t)(b * NTOT + dst)) * CIN + cs;
    __nv_bfloat16* dl = (mode == 0 ? g_xl : g_pl) + ((size_t)(b * NTOT + dst)) * CIN + cs;
    __align__(16) __nv_bfloat16 hb[16], lb[16];
    #pragma unroll
    for (int i = 0; i < 16; ++i) split_bf16(S[cs + i][n], hb[i], lb[i]);
    *(uint4*)dh       = *(uint4*)hb;
    *(uint4*)(dh + 8) = *(uint4*)(hb + 8);
    *(uint4*)dl       = *(uint4*)lb;
    *(uint4*)(dl + 8) = *(uint4*)(lb + 8);
}

// ============================================================
// K2: projections on tensor cores (3-term bf16 split),
//     X consumed (n,c) via non-trans ldmatrix B.
//     outputs: skip fp32 -> d_out; q/k tf32 (p,n,d') d-interleaved;
//     v tf32 (p,d,n)
// ============================================================
#define PWH 0
#define PWL 17408
#define PXH 34816
#define PXL 69632
#define SMEM_PROJ 104448

__global__ __launch_bounds__(256, 2) void proj_kernel(
    const float* __restrict__ Wq, const float* __restrict__ Wk,
    const float* __restrict__ Wv, const float* __restrict__ Wskip,
    float* __restrict__ out)
{
    extern __shared__ __align__(1024) char smem[];
    uint32_t sb = smem_u32(smem);
    int tid = threadIdx.x, wid = tid >> 5, lane = tid & 31;
    int nb = blockIdx.x, ob = blockIdx.y, b = blockIdx.z;
    int m = ob >> 2, h = ob & 3;
    int p = b * NH + h;

    const float* W = (m == 0 ? Wq : m == 1 ? Wk : m == 2 ? Wv : Wskip) + h * 64 * CIN;
    const __nv_bfloat16* Xh = (m == 3 ? g_ph : g_xh) + ((size_t)b * NTOT + nb * 128) * CIN;
    const __nv_bfloat16* Xl = (m == 3 ? g_pl : g_xl) + ((size_t)b * NTOT + nb * 128) * CIN;

    // ---- W fp32 -> smem bf16 hi/lo (64 x 128, pitch 272) ----
    #pragma unroll
    for (int l = 0; l < 8; ++l) {
        int idx = tid + l * 256;                   // 2048 float4
        int o = idx >> 5, c4 = (idx & 31) * 4;
        float4 w = *(const float4*)(W + o * 128 + c4);
        __nv_bfloat16 h0, h1, h2, h3, l0, l1, l2, l3;
        split_bf16(w.x, h0, l0); split_bf16(w.y, h1, l1);
        split_bf16(w.z, h2, l2); split_bf16(w.w, h3, l3);
        __nv_bfloat162* dh = (__nv_bfloat162*)(smem + PWH + o * 272 + c4 * 2);
        __nv_bfloat162* dl = (__nv_bfloat162*)(smem + PWL + o * 272 + c4 * 2);
        dh[0] = {h0, h1}; dh[1] = {h2, h3};
        dl[0] = {l0, l1}; dl[1] = {l2, l3};
    }
    // ---- X tiles: 128 n-rows x 256B, pitch 272 ----
    #pragma unroll
    for (int l = 0; l < 8; ++l) {
        int idx = tid + l * 256;                   // 2048 uint4
        int n = idx >> 4, u = idx & 15;
        *(uint4*)(smem + PXH + n * 272 + u * 16) = ((const uint4*)(Xh + (size_t)n * CIN))[u];
        *(uint4*)(smem + PXL + n * 272 + u * 16) = ((const uint4*)(Xl + (size_t)n * CIN))[u];
    }
    __syncthreads();

    int mw = wid & 3, nw = wid >> 2;
    uint32_t wa = sb + PWH + (mw * 16 + (lane & 15)) * 272 + (lane >> 4) * 16;
    uint32_t xb = sb + PXH + (((lane & 7) | ((lane & 16) >> 1)) + nw * 64) * 272
                + ((lane >> 3) & 1) * 16;
    float acc[8][4] = {};

    #pragma unroll
    for (int kt = 0; kt < 8; ++kt) {
        uint32_t ah[4], al[4];
        ldsm_x4(ah[0], ah[1], ah[2], ah[3], wa + kt * 32);
        ldsm_x4(al[0], al[1], al[2], al[3], wa + (PWL - PWH) + kt * 32);
        #pragma unroll
        for (int nt = 0; nt < 4; ++nt) {
            uint32_t bh[4], bl[4];
            uint32_t base = xb + nt * (16 * 272) + kt * 32;
            ldsm_x4(bh[0], bh[1], bh[2], bh[3], base);
            ldsm_x4(bl[0], bl[1], bl[2], bl[3], base + (PXL - PXH));
            mma16816(acc[2 * nt],     ah, bh[0], bh[1]);
            mma16816(acc[2 * nt + 1], ah, bh[2], bh[3]);
            mma16816(acc[2 * nt],     al, bh[0], bh[1]);
            mma16816(acc[2 * nt + 1], al, bh[2], bh[3]);
            mma16816(acc[2 * nt],     ah, bl[0], bl[1]);
            mma16816(acc[2 * nt + 1], ah, bl[2], bl[3]);
        }
    }

    if (m == 3) {                                  // skip -> d_out (fp32, exact)
        #pragma unroll
        for (int g = 0; g < 8; ++g) {
            int n_g = nb * 128 + nw * 64 + g * 8 + (lane & 3) * 2;
            #pragma unroll
            for (int cc = 0; cc < 2; ++cc) {
                int o_g = h * 64 + mw * 16 + (lane >> 2) + cc * 8;
                float2 st = {acc[g][2 * cc], acc[g][2 * cc + 1]};
                *(float2*)(out + ((size_t)(b * OUTC + o_g)) * NTOT + n_g) = st;
            }
        }
    } else if (m == 2) {                           // v: stage [d][n] pitch 132 -> (p,d,n)
        __syncthreads();
        float* S = (float*)smem;
        #pragma unroll
        for (int g = 0; g < 8; ++g) {
            int n0 = nw * 64 + g * 8 + (lane & 3) * 2;
            #pragma unroll
            for (int cc = 0; cc < 2; ++cc) {
                int d = mw * 16 + (lane >> 2) + cc * 8;
                #pragma unroll
                for (int e = 0; e < 2; ++e)
                    S[d * 132 + n0 + e] = tf32r(acc[g][2 * cc + e]);
            }
        }
        __syncthreads();
        float* dst = g_v + (size_t)p * HD * NTOT + nb * 128;
        #pragma unroll
        for (int l = 0; l < 8; ++l) {
            int idx = tid + l * 256;               // 2048 float4: 64 d x 32
            int d = idx >> 5, u = idx & 31;
            *(float4*)(dst + (size_t)d * NTOT + u * 4) = *(float4*)&S[d * 132 + u * 4];
        }
    } else {                                       // q/k: stage [n][d'] pitch 72 -> (p,n,d')
        float scale = (m == 0) ? 0.125f : 1.0f;
        __syncthreads();
        float* S = (float*)smem;
        #pragma unroll
        for (int g = 0; g < 8; ++g) {
            int n0 = nw * 64 + g * 8 + (lane & 3) * 2;
            #pragma unroll
            for (int cc = 0; cc < 2; ++cc) {
                int d = mw * 16 + (lane >> 2) + cc * 8;
                int dp = (d & ~7) | (((d & 3) << 1) | ((d >> 2) & 1));   // interleave within 8
                #pragma unroll
                for (int e = 0; e < 2; ++e)
                    S[(n0 + e) * 72 + dp] = tf32r(acc[g][2 * cc + e] * scale);
            }
        }
        __syncthreads();
        float* dst = (m == 0 ? g_q : g_k) + ((size_t)p * NTOT + nb * 128) * HD;
        #pragma unroll
        for (int l = 0; l < 8; ++l) {
            int idx = tid + l * 256;               // 2048 float4: 128 n x 16
            int n = idx >> 4, u = idx & 15;
            *(float4*)(dst + n * HD + u * 4) = *(float4*)&S[n * 72 + u * 4];
        }
    }
}

// ============================================================
// K3: fused flash attention, tf32, float2 fragments, no shuffles
//     4 warps x M=32 = 128 rows/CTA, 2 CTAs/SM, grid (16 it, 16 p)
// ============================================================
#define AQ  0
#define AK0 36864
#define AK1 55296
#define AV0 73728
#define AV1 92160
#define SMEM_ATTN 110592
#define PIT 288

__device__ __forceinline__ void load_kv(uint32_t sb, int p, int c, int s, int tid) {
    const char* gk = (const char*)(g_k + ((size_t)p * NTOT + c * 64) * HD);
    const char* gv = (const char*)(g_v + (size_t)p * HD * NTOT + c * 64);
    uint32_t kd = sb + (s ? AK1 : AK0);
    uint32_t vd = sb + (s ? AV1 : AV0);
    #pragma unroll
    for (int l = 0; l < 8; ++l) {
        int idx = tid + l * 128;                   // 1024 x 16B each
        int row = idx >> 4, c16 = (idx & 15) * 16;
        CP16(kd + row * PIT + c16, gk + (size_t)row * (HD * 4) + c16);
        CP16(vd + row * PIT + c16, gv + (size_t)row * (NTOT * 4) + c16);
    }
}

__global__ __launch_bounds__(128, 2) void attn_kernel(float* __restrict__ out)
{
    extern __shared__ __align__(1024) char smem[];
    uint32_t sb = smem_u32(smem);
    int tid = threadIdx.x, wid = tid >> 5, lane = tid & 31;
    int g = lane >> 2, t = lane & 3;
    int it = blockIdx.x, p = blockIdx.y;
    int b = p >> 2, h = p & 3;

    // ---- issue Q (128 rows x 256B) + chunk0 as group 0 ----
    {
        const char* gq = (const char*)(g_q + ((size_t)p * NTOT + it * 128) * HD);
        #pragma unroll
        for (int l = 0; l < 16; ++l) {
            int idx = tid + l * 128;               // 2048 x 16B
            int row = idx >> 4, c16 = (idx & 15) * 16;
            CP16(sb + AQ + row * PIT + c16, gq + (size_t)row * (HD * 4) + c16);
        }
        load_kv(sb, p, 0, 0, tid);
        CP_COMMIT();
    }

    float o[2][8][4] = {};
    float rs[2][2] = {};
    int fragc = (2 * t) * 4;                       // byte col of (t, t+4) pair (interleaved)

    for (int c = 0; c < NCHUNK; ++c) {
        if (c) __syncthreads();
        if (c < NCHUNK - 1) {
            load_kv(sb, p, c + 1, (c + 1) & 1, tid);
            CP_COMMIT();
            CP_WAIT(1);
        } else {
            CP_WAIT(0);
        }
        __syncthreads();

        const char* kbp = smem + ((c & 1) ? AK1 : AK0);
        const char* vbp = smem + ((c & 1) ? AV1 : AV0);

        // ---- S = Q Kᵀ, float2 fragment loads ----
        float s[2][8][4] = {};
        #pragma unroll
        for (int ks = 0; ks < 8; ++ks) {
            float a[2][4];
            #pragma unroll
            for (int mi = 0; mi < 2; ++mi) {
                const char* ra = smem + AQ + (wid * 32 + mi * 16 + g) * PIT + ks * 32 + fragc;
                float2 lo = *(const float2*)ra;
                float2 hi = *(const float2*)(ra + 8 * PIT);
                a[mi][0] = lo.x; a[mi][2] = lo.y;
                a[mi][1] = hi.x; a[mi][3] = hi.y;
            }
            #pragma unroll
            for (int jt = 0; jt < 8; ++jt) {
                float2 bb = *(const float2*)(kbp + (jt * 8 + g) * PIT + ks * 32 + fragc);
                mma1688(s[0][jt], a[0][0], a[0][1], a[0][2], a[0][3], bb.x, bb.y);
                mma1688(s[1][jt], a[1][0], a[1][1], a[1][2], a[1][3], bb.x, bb.y);
            }
        }

        // ---- exp + tf32 round + rowsum ----
        #pragma unroll
        for (int mi = 0; mi < 2; ++mi) {
            #pragma unroll
            for (int jt = 0; jt < 8; ++jt) {
                float p0 = tf32r(__expf(s[mi][jt][0]));
                float p1 = tf32r(__expf(s[mi][jt][1]));
                float p2 = tf32r(__expf(s[mi][jt][2]));
                float p3 = tf32r(__expf(s[mi][jt][3]));
                rs[mi][0] += p0 + p1;
                rs[mi][1] += p2 + p3;
                s[mi][jt][0] = p0; s[mi][jt][1] = p1;
                s[mi][jt][2] = p2; s[mi][jt][3] = p3;
            }
        }

        // ---- O += P V : c-frag used directly as A-frag (k-slot t <-> j=2t);
        //      B = V[j=2t], V[j=2t+1] = contiguous float2 in natural layout ----
        #pragma unroll
        for (int ks = 0; ks < 8; ++ks) {
            #pragma unroll
            for (int dt = 0; dt < 8; ++dt) {
                float2 bb = *(const float2*)(vbp + (dt * 8 + g) * PIT + ks * 32 + fragc);
                mma1688(o[0][dt], s[0][ks][0], s[0][ks][2], s[0][ks][1], s[0][ks][3], bb.x, bb.y);
                mma1688(o[1][dt], s[1][ks][0], s[1][ks][2], s[1][ks][1], s[1][ks][3], bb.x, bb.y);
            }
        }
    }

    // ---- rowsum reduce across quad, normalize, transpose via smem ----
    float inv[2][2];
    #pragma unroll
    for (int mi = 0; mi < 2; ++mi) {
        #pragma unroll
        for (int cc = 0; cc < 2; ++cc) {
            float v = rs[mi][cc];
            v += __shfl_xor_sync(0xffffffffu, v, 1);
            v += __shfl_xor_sync(0xffffffffu, v, 2);
            inv[mi][cc] = 1.0f / v;
        }
    }

    __syncthreads();
    float* Os = (float*)smem;                      // [64][129]
    #pragma unroll
    for (int mi = 0; mi < 2; ++mi) {
        int i0 = wid * 32 + mi * 16 + g;
        #pragma unroll
        for (int dt = 0; dt < 8; ++dt) {
            int d0 = dt * 8 + t * 2;
            Os[d0 * 129 + i0]           = o[mi][dt][0] * inv[mi][0];
            Os[(d0 + 1) * 129 + i0]     = o[mi][dt][1] * inv[mi][0];
            Os[d0 * 129 + i0 + 8]       = o[mi][dt][2] * inv[mi][1];
            Os[(d0 + 1) * 129 + i0 + 8] = o[mi][dt][3] * inv[mi][1];
        }
    }
    __syncthreads();

    #pragma unroll
    for (int l = 0; l < 64; ++l) {
        int idx = tid + l * 128;                   // 8192 elements
        int i = idx & 127, d = idx >> 7;
        size_t go = ((size_t)(b * OUTC + h * HD + d)) * NTOT + it * 128 + i;
        out[go] += Os[d * 129 + i];
    }
}

// ============================================================
extern "C" void kernel_launch(void* const* d_in, const int* in_sizes, int n_in,
                              void* d_out, int out_size)
{
    const float* pcd   = (const float*)d_in[0];
    const float* sel   = (const float*)d_in[1];
    const float* drp   = (const float*)d_in[2];
    const int*   isel  = (const int*)d_in[3];
    const int*   idrp  = (const int*)d_in[4];
    const float* Wq    = (const float*)d_in[5];
    const float* Wk    = (const float*)d_in[6];
    const float* Wv    = (const float*)d_in[7];
    const float* Wskip = (const float*)d_in[8];
    float* out = (float*)d_out;

    cudaFuncSetAttribute(proj_kernel, cudaFuncAttributeMaxDynamicSharedMemorySize, SMEM_PROJ);
    cudaFuncSetAttribute(attn_kernel, cudaFuncAttributeMaxDynamicSharedMemorySize, SMEM_ATTN);

    prep_kernel<<<dim3(64, 2, NB), 256>>>(sel, drp, isel, idrp, pcd);
    proj_kernel<<<dim3(16, 16, NB), 256, SMEM_PROJ>>>(Wq, Wk, Wv, Wskip, out);
    attn_kernel<<<dim3(16, NP), 128, SMEM_ATTN>>>(out);
}

// round 10
// speedup vs baseline: 8.0646x; 1.6417x over previous
#include <cuda_runtime.h>
#include <cuda_bf16.h>
#include <cuda_fp16.h>
#include <cstdint>

#define NB   4
#define CIN  128
#define NTOT 2048
#define NH   4
#define HD   64
#define OUTC 256
#define NP   16
#define NCHUNK 32

// ---------------- scratch ----------------
__device__ __nv_bfloat16 g_xh[NB * NTOT * CIN];        // scattered input hi (b,n,c)
__device__ __nv_bfloat16 g_xl[NB * NTOT * CIN];        // scattered input lo
__device__ __nv_bfloat16 g_ph[NB * NTOT * CIN];        // pcd_up hi (b,n,c)
__device__ __nv_bfloat16 g_pl[NB * NTOT * CIN];        // pcd_up lo
__device__ __half g_q[NP * NTOT * HD];                 // (p,n,d) fp16, pre-scaled 1/8
__device__ __half g_k[NP * NTOT * HD];                 // (p,n,d) fp16
__device__ __half g_v[NP * NTOT * HD];                 // (p,n,d) fp16

// ---------------- helpers ----------------
__device__ __forceinline__ uint32_t smem_u32(const void* p) {
    uint32_t a;
    asm("{ .reg .u64 t; cvta.to.shared.u64 t, %1; cvt.u32.u64 %0, t; }" : "=r"(a) : "l"(p));
    return a;
}
__device__ __forceinline__ void ldsm_x4(uint32_t& r0, uint32_t& r1, uint32_t& r2, uint32_t& r3,
                                        uint32_t addr) {
    asm volatile("ldmatrix.sync.aligned.m8n8.x4.shared.b16 {%0,%1,%2,%3}, [%4];"
                 : "=r"(r0), "=r"(r1), "=r"(r2), "=r"(r3) : "r"(addr));
}
__device__ __forceinline__ void ldsm_x4_t(uint32_t& r0, uint32_t& r1, uint32_t& r2, uint32_t& r3,
                                          uint32_t addr) {
    asm volatile("ldmatrix.sync.aligned.m8n8.x4.trans.shared.b16 {%0,%1,%2,%3}, [%4];"
                 : "=r"(r0), "=r"(r1), "=r"(r2), "=r"(r3) : "r"(addr));
}
__device__ __forceinline__ void mma16816(float* d, const uint32_t* a, uint32_t b0, uint32_t b1) {
    asm volatile("mma.sync.aligned.m16n8k16.row.col.f32.bf16.bf16.f32 "
                 "{%0,%1,%2,%3}, {%4,%5,%6,%7}, {%8,%9}, {%0,%1,%2,%3};"
                 : "+f"(d[0]), "+f"(d[1]), "+f"(d[2]), "+f"(d[3])
                 : "r"(a[0]), "r"(a[1]), "r"(a[2]), "r"(a[3]), "r"(b0), "r"(b1));
}
__device__ __forceinline__ void mma16816h(float* d, const uint32_t* a, uint32_t b0, uint32_t b1) {
    asm volatile("mma.sync.aligned.m16n8k16.row.col.f32.f16.f16.f32 "
                 "{%0,%1,%2,%3}, {%4,%5,%6,%7}, {%8,%9}, {%0,%1,%2,%3};"
                 : "+f"(d[0]), "+f"(d[1]), "+f"(d[2]), "+f"(d[3])
                 : "r"(a[0]), "r"(a[1]), "r"(a[2]), "r"(a[3]), "r"(b0), "r"(b1));
}
#define CP16(dst, src) asm volatile("cp.async.cg.shared.global [%0], [%1], 16;" :: "r"(dst), "l"(src))
#define CP_COMMIT()    asm volatile("cp.async.commit_group;" ::: "memory")
#define CP_WAIT(n)     asm volatile("cp.async.wait_group %0;" :: "n"(n) : "memory")

__device__ __forceinline__ void split_bf16(float x, __nv_bfloat16& hi, __nv_bfloat16& lo) {
    hi = __float2bfloat16(x);
    lo = __float2bfloat16(x - __bfloat162float(hi));
}

// ============================================================
// K1: tiled transpose + scatter -> (b,n,c) bf16 hi/lo
// ============================================================
__global__ __launch_bounds__(256) void prep_kernel(
    const float* __restrict__ sel, const float* __restrict__ drp,
    const int* __restrict__ isel, const int* __restrict__ idrp,
    const float* __restrict__ pcd)
{
    __shared__ float S[128][33];
    __shared__ int dsts[32];
    int tx = blockIdx.x, mode = blockIdx.y, b = blockIdx.z;
    int t = threadIdx.x;

    if (mode == 0) {
        const float* src; const int* ip; int n0;
        if (tx < 32) { src = sel + (size_t)b * CIN * 1024; ip = isel; n0 = tx * 32; }
        else         { src = drp + (size_t)b * CIN * 1024; ip = idrp; n0 = tx * 32 - 1024; }
        #pragma unroll
        for (int i = 0; i < 16; ++i) {
            int idx = t + i * 256;
            int c = idx >> 5, n = idx & 31;
            S[c][n] = src[(size_t)c * 1024 + n0 + n];
        }
        if (t < 32) dsts[t] = ip[b * 1024 + n0 + t];
    } else {
        int n0 = tx * 32;
        #pragma unroll
        for (int i = 0; i < 16; ++i) {
            int idx = t + i * 256;
            int c = idx >> 5, n = idx & 31;
            S[c][n] = pcd[((size_t)b * CIN + c) * NTOT + n0 + n];
        }
        if (t < 32) dsts[t] = n0 + t;
    }
    __syncthreads();

    int n = t >> 3, cs = (t & 7) * 16;
    int dst = dsts[n];
    __nv_bfloat16* dh = (mode == 0 ? g_xh : g_ph) + ((size_t)(b * NTOT + dst)) * CIN + cs;
    __nv_bfloat16* dl = (mode == 0 ? g_xl : g_pl) + ((size_t)(b * NTOT + dst)) * CIN + cs;
    __align__(16) __nv_bfloat16 hb[16], lb[16];
    #pragma unroll
    for (int i = 0; i < 16; ++i) split_bf16(S[cs + i][n], hb[i], lb[i]);
    *(uint4*)dh       = *(uint4*)hb;
    *(uint4*)(dh + 8) = *(uint4*)(hb + 8);
    *(uint4*)dl       = *(uint4*)lb;
    *(uint4*)(dl + 8) = *(uint4*)(lb + 8);
}

// ============================================================
// K2: projections on tensor cores (3-term bf16 split inputs)
//     outputs: skip fp32 -> d_out; q/k/v fp16 (p,n,d)
// ============================================================
#define PWH 0
#define PWL 17408
#define PXH 34816
#define PXL 69632
#define SMEM_PROJ 104448

__global__ __launch_bounds__(256, 2) void proj_kernel(
    const float* __restrict__ Wq, const float* __restrict__ Wk,
    const float* __restrict__ Wv, const float* __restrict__ Wskip,
    float* __restrict__ out)
{
    extern __shared__ __align__(1024) char smem[];
    uint32_t sb = smem_u32(smem);
    int tid = threadIdx.x, wid = tid >> 5, lane = tid & 31;
    int nb = blockIdx.x, ob = blockIdx.y, b = blockIdx.z;
    int m = ob >> 2, h = ob & 3;
    int p = b * NH + h;

    const float* W = (m == 0 ? Wq : m == 1 ? Wk : m == 2 ? Wv : Wskip) + h * 64 * CIN;
    const __nv_bfloat16* Xh = (m == 3 ? g_ph : g_xh) + ((size_t)b * NTOT + nb * 128) * CIN;
    const __nv_bfloat16* Xl = (m == 3 ? g_pl : g_xl) + ((size_t)b * NTOT + nb * 128) * CIN;

    #pragma unroll
    for (int l = 0; l < 8; ++l) {
        int idx = tid + l * 256;                   // 2048 float4
        int o = idx >> 5, c4 = (idx & 31) * 4;
        float4 w = *(const float4*)(W + o * 128 + c4);
        __nv_bfloat16 h0, h1, h2, h3, l0, l1, l2, l3;
        split_bf16(w.x, h0, l0); split_bf16(w.y, h1, l1);
        split_bf16(w.z, h2, l2); split_bf16(w.w, h3, l3);
        __nv_bfloat162* dh = (__nv_bfloat162*)(smem + PWH + o * 272 + c4 * 2);
        __nv_bfloat162* dl = (__nv_bfloat162*)(smem + PWL + o * 272 + c4 * 2);
        dh[0] = {h0, h1}; dh[1] = {h2, h3};
        dl[0] = {l0, l1}; dl[1] = {l2, l3};
    }
    #pragma unroll
    for (int l = 0; l < 8; ++l) {
        int idx = tid + l * 256;                   // 2048 uint4
        int n = idx >> 4, u = idx & 15;
        *(uint4*)(smem + PXH + n * 272 + u * 16) = ((const uint4*)(Xh + (size_t)n * CIN))[u];
        *(uint4*)(smem + PXL + n * 272 + u * 16) = ((const uint4*)(Xl + (size_t)n * CIN))[u];
    }
    __syncthreads();

    int mw = wid & 3, nw = wid >> 2;
    uint32_t wa = sb + PWH + (mw * 16 + (lane & 15)) * 272 + (lane >> 4) * 16;
    uint32_t xb = sb + PXH + (((lane & 7) | ((lane & 16) >> 1)) + nw * 64) * 272
                + ((lane >> 3) & 1) * 16;
    float acc[8][4] = {};

    #pragma unroll
    for (int kt = 0; kt < 8; ++kt) {
        uint32_t ah[4], al[4];
        ldsm_x4(ah[0], ah[1], ah[2], ah[3], wa + kt * 32);
        ldsm_x4(al[0], al[1], al[2], al[3], wa + (PWL - PWH) + kt * 32);
        #pragma unroll
        for (int nt = 0; nt < 4; ++nt) {
            uint32_t bh[4], bl[4];
            uint32_t base = xb + nt * (16 * 272) + kt * 32;
            ldsm_x4(bh[0], bh[1], bh[2], bh[3], base);
            ldsm_x4(bl[0], bl[1], bl[2], bl[3], base + (PXL - PXH));
            mma16816(acc[2 * nt],     ah, bh[0], bh[1]);
            mma16816(acc[2 * nt + 1], ah, bh[2], bh[3]);
            mma16816(acc[2 * nt],     al, bh[0], bh[1]);
            mma16816(acc[2 * nt + 1], al, bh[2], bh[3]);
            mma16816(acc[2 * nt],     ah, bl[0], bl[1]);
            mma16816(acc[2 * nt + 1], ah, bl[2], bl[3]);
        }
    }

    if (m == 3) {                                  // skip -> d_out (fp32, exact)
        #pragma unroll
        for (int g = 0; g < 8; ++g) {
            int n_g = nb * 128 + nw * 64 + g * 8 + (lane & 3) * 2;
            #pragma unroll
            for (int cc = 0; cc < 2; ++cc) {
                int o_g = h * 64 + mw * 16 + (lane >> 2) + cc * 8;
                float2 st = {acc[g][2 * cc], acc[g][2 * cc + 1]};
                *(float2*)(out + ((size_t)(b * OUTC + o_g)) * NTOT + n_g) = st;
            }
        }
    } else {                                       // q/k/v: stage [n][d] fp16 pitch 72h -> (p,n,d)
        float scale = (m == 0) ? 0.125f : 1.0f;
        __syncthreads();
        __half* S = (__half*)smem;
        #pragma unroll
        for (int g = 0; g < 8; ++g) {
            int n0 = nw * 64 + g * 8 + (lane & 3) * 2;
            #pragma unroll
            for (int cc = 0; cc < 2; ++cc) {
                int d = mw * 16 + (lane >> 2) + cc * 8;
                #pragma unroll
                for (int e = 0; e < 2; ++e)
                    S[(n0 + e) * 72 + d] = __float2half_rn(acc[g][2 * cc + e] * scale);
            }
        }
        __syncthreads();
        __half* dst = (m == 0 ? g_q : m == 1 ? g_k : g_v) + ((size_t)p * NTOT + nb * 128) * HD;
        #pragma unroll
        for (int l = 0; l < 4; ++l) {
            int idx = tid + l * 256;               // 1024 uint4 (128 rows x 128 B)
            int n = idx >> 3, u = idx & 7;
            ((uint4*)dst)[idx] = *(const uint4*)((char*)S + n * 144 + u * 16);
        }
    }
}

// ============================================================
// K3: fused flash attention, single-term fp16 HMMA
//     4 warps x M=32 = 128 rows/CTA, 2 CTAs/SM, grid (16 it, 16 p)
// ============================================================
#define PIT 144
#define AQ  0
#define AK0 18432
#define AK1 27648
#define AV0 36864
#define AV1 46080
#define SMEM_ATTN 55296

__device__ __forceinline__ void load_kv(uint32_t sb, int p, int c, int s, int tid) {
    const char* gk = (const char*)(g_k + ((size_t)p * NTOT + c * 64) * HD);
    const char* gv = (const char*)(g_v + ((size_t)p * NTOT + c * 64) * HD);
    uint32_t kd = sb + (s ? AK1 : AK0);
    uint32_t vd = sb + (s ? AV1 : AV0);
    #pragma unroll
    for (int l = 0; l < 4; ++l) {
        int idx = tid + l * 128;                   // 512 x 16B each
        int row = idx >> 3, c16 = (idx & 7) * 16;
        CP16(kd + row * PIT + c16, gk + row * 128 + c16);
        CP16(vd + row * PIT + c16, gv + row * 128 + c16);
    }
}

__global__ __launch_bounds__(128, 2) void attn_kernel(float* __restrict__ out)
{
    extern __shared__ __align__(1024) char smem[];
    uint32_t sb = smem_u32(smem);
    int tid = threadIdx.x, wid = tid >> 5, lane = tid & 31;
    int g = lane >> 2, t = lane & 3;
    int it = blockIdx.x, p = blockIdx.y;
    int b = p >> 2, h = p & 3;

    // ---- issue Q (128 rows x 128B) + chunk0 as group 0 ----
    {
        const char* gq = (const char*)(g_q + ((size_t)p * NTOT + it * 128) * HD);
        #pragma unroll
        for (int l = 0; l < 8; ++l) {
            int idx = tid + l * 128;               // 1024 x 16B
            int row = idx >> 3, c16 = (idx & 7) * 16;
            CP16(sb + AQ + row * PIT + c16, gq + row * 128 + c16);
        }
        load_kv(sb, p, 0, 0, tid);
        CP_COMMIT();
    }

    uint32_t qa = sb + AQ + (wid * 32 + (lane & 15)) * PIT + (lane >> 4) * 16;
    uint32_t kb_rel = ((lane & 7) | ((lane & 16) >> 1)) * PIT + ((lane >> 3) & 1) * 16;
    uint32_t vb_rel = (lane & 15) * PIT + (lane >> 4) * 16;

    float o[2][8][4] = {};
    float rs[2][2] = {};

    for (int c = 0; c < NCHUNK; ++c) {
        if (c) __syncthreads();
        if (c < NCHUNK - 1) {
            load_kv(sb, p, c + 1, (c + 1) & 1, tid);
            CP_COMMIT();
            CP_WAIT(1);
        } else {
            CP_WAIT(0);
        }
        __syncthreads();

        uint32_t kb = sb + ((c & 1) ? AK1 : AK0) + kb_rel;
        uint32_t vb = sb + ((c & 1) ? AV1 : AV0) + vb_rel;

        // ---- S = Q Kᵀ (single-term fp16) ----
        float s[2][8][4] = {};
        #pragma unroll
        for (int kt = 0; kt < 4; ++kt) {
            uint32_t aq[2][4];
            #pragma unroll
            for (int mi = 0; mi < 2; ++mi)
                ldsm_x4(aq[mi][0], aq[mi][1], aq[mi][2], aq[mi][3],
                        qa + mi * (16 * PIT) + kt * 32);
            #pragma unroll
            for (int nt2 = 0; nt2 < 4; ++nt2) {
                uint32_t bh[4];
                ldsm_x4(bh[0], bh[1], bh[2], bh[3], kb + nt2 * (16 * PIT) + kt * 32);
                #pragma unroll
                for (int mi = 0; mi < 2; ++mi) {
                    mma16816h(s[mi][2 * nt2],     aq[mi], bh[0], bh[1]);
                    mma16816h(s[mi][2 * nt2 + 1], aq[mi], bh[2], bh[3]);
                }
            }
        }

        // ---- per-kt: exp + fp16 pack, then P·V (V via trans-ldmatrix) ----
        #pragma unroll
        for (int kt = 0; kt < 4; ++kt) {
            uint32_t ph[2][4];
            #pragma unroll
            for (int mi = 0; mi < 2; ++mi) {
                #pragma unroll
                for (int hf = 0; hf < 2; ++hf) {
                    float* sv = s[mi][2 * kt + hf];
                    float e0 = __expf(sv[0]), e1 = __expf(sv[1]);
                    float e2 = __expf(sv[2]), e3 = __expf(sv[3]);
                    rs[mi][0] += e0 + e1; rs[mi][1] += e2 + e3;
                    uint32_t h01, h23;
                    asm("cvt.rn.f16x2.f32 %0, %1, %2;" : "=r"(h01) : "f"(e1), "f"(e0));
                    asm("cvt.rn.f16x2.f32 %0, %1, %2;" : "=r"(h23) : "f"(e3), "f"(e2));
                    ph[mi][2 * hf] = h01; ph[mi][2 * hf + 1] = h23;
                }
            }
            #pragma unroll
            for (int nt2 = 0; nt2 < 4; ++nt2) {
                uint32_t bh[4];
                ldsm_x4_t(bh[0], bh[1], bh[2], bh[3], vb + kt * (16 * PIT) + nt2 * 32);
                #pragma unroll
                for (int mi = 0; mi < 2; ++mi) {
                    mma16816h(o[mi][2 * nt2],     ph[mi], bh[0], bh[1]);
                    mma16816h(o[mi][2 * nt2 + 1], ph[mi], bh[2], bh[3]);
                }
            }
        }
    }

    // ---- rowsum reduce across quad, normalize, transpose via smem ----
    float inv[2][2];
    #pragma unroll
    for (int mi = 0; mi < 2; ++mi) {
        #pragma unroll
        for (int cc = 0; cc < 2; ++cc) {
            float v = rs[mi][cc];
            v += __shfl_xor_sync(0xffffffffu, v, 1);
            v += __shfl_xor_sync(0xffffffffu, v, 2);
            inv[mi][cc] = 1.0f / v;
        }
    }

    __syncthreads();
    float* Os = (float*)smem;                      // [64][129]
    #pragma unroll
    for (int mi = 0; mi < 2; ++mi) {
        int i0 = wid * 32 + mi * 16 + g;
        #pragma unroll
        for (int dt = 0; dt < 8; ++dt) {
            int d0 = dt * 8 + t * 2;
            Os[d0 * 129 + i0]           = o[mi][dt][0] * inv[mi][0];
            Os[(d0 + 1) * 129 + i0]     = o[mi][dt][1] * inv[mi][0];
            Os[d0 * 129 + i0 + 8]       = o[mi][dt][2] * inv[mi][1];
            Os[(d0 + 1) * 129 + i0 + 8] = o[mi][dt][3] * inv[mi][1];
        }
    }
    __syncthreads();

    #pragma unroll
    for (int l = 0; l < 64; ++l) {
        int idx = tid + l * 128;                   // 8192 elements
        int i = idx & 127, d = idx >> 7;
        size_t go = ((size_t)(b * OUTC + h * HD + d)) * NTOT + it * 128 + i;
        out[go] += Os[d * 129 + i];
    }
}

// ============================================================
extern "C" void kernel_launch(void* const* d_in, const int* in_sizes, int n_in,
                              void* d_out, int out_size)
{
    const float* pcd   = (const float*)d_in[0];
    const float* sel   = (const float*)d_in[1];
    const float* drp   = (const float*)d_in[2];
    const int*   isel  = (const int*)d_in[3];
    const int*   idrp  = (const int*)d_in[4];
    const float* Wq    = (const float*)d_in[5];
    const float* Wk    = (const float*)d_in[6];
    const float* Wv    = (const float*)d_in[7];
    const float* Wskip = (const float*)d_in[8];
    float* out = (float*)d_out;

    cudaFuncSetAttribute(proj_kernel, cudaFuncAttributeMaxDynamicSharedMemorySize, SMEM_PROJ);
    cudaFuncSetAttribute(attn_kernel, cudaFuncAttributeMaxDynamicSharedMemorySize, SMEM_ATTN);

    prep_kernel<<<dim3(64, 2, NB), 256>>>(sel, drp, isel, idrp, pcd);
    proj_kernel<<<dim3(16, 16, NB), 256, SMEM_PROJ>>>(Wq, Wk, Wv, Wskip, out);
    attn_kernel<<<dim3(16, NP), 128, SMEM_ATTN>>>(out);
}

// round 11
// speedup vs baseline: 9.0760x; 1.1254x over previous
#include <cuda_runtime.h>
#include <cuda_bf16.h>
#include <cuda_fp16.h>
#include <cstdint>

#define NB   4
#define CIN  128
#define NTOT 2048
#define NH   4
#define HD   64
#define OUTC 256
#define NP   16
#define NCHUNK 32

// ---------------- scratch ----------------
__device__ __half g_x[NB * NTOT * CIN];                // scattered input fp16 (b,n,c)
__device__ __nv_bfloat16 g_ph[NB * NTOT * CIN];        // pcd_up hi (b,n,c)
__device__ __nv_bfloat16 g_pl[NB * NTOT * CIN];        // pcd_up lo
__device__ __half g_q[NP * NTOT * HD];                 // (p,n,d) fp16, pre-scaled 1/8
__device__ __half g_k[NP * NTOT * HD];                 // (p,n,d) fp16
__device__ __half g_v[NP * NTOT * HD];                 // (p,n,d) fp16

// ---------------- helpers ----------------
__device__ __forceinline__ uint32_t smem_u32(const void* p) {
    uint32_t a;
    asm("{ .reg .u64 t; cvta.to.shared.u64 t, %1; cvt.u32.u64 %0, t; }" : "=r"(a) : "l"(p));
    return a;
}
__device__ __forceinline__ void ldsm_x4(uint32_t& r0, uint32_t& r1, uint32_t& r2, uint32_t& r3,
                                        uint32_t addr) {
    asm volatile("ldmatrix.sync.aligned.m8n8.x4.shared.b16 {%0,%1,%2,%3}, [%4];"
                 : "=r"(r0), "=r"(r1), "=r"(r2), "=r"(r3) : "r"(addr));
}
__device__ __forceinline__ void ldsm_x4_t(uint32_t& r0, uint32_t& r1, uint32_t& r2, uint32_t& r3,
                                          uint32_t addr) {
    asm volatile("ldmatrix.sync.aligned.m8n8.x4.trans.shared.b16 {%0,%1,%2,%3}, [%4];"
                 : "=r"(r0), "=r"(r1), "=r"(r2), "=r"(r3) : "r"(addr));
}
__device__ __forceinline__ void mma16816(float* d, const uint32_t* a, uint32_t b0, uint32_t b1) {
    asm volatile("mma.sync.aligned.m16n8k16.row.col.f32.bf16.bf16.f32 "
                 "{%0,%1,%2,%3}, {%4,%5,%6,%7}, {%8,%9}, {%0,%1,%2,%3};"
                 : "+f"(d[0]), "+f"(d[1]), "+f"(d[2]), "+f"(d[3])
                 : "r"(a[0]), "r"(a[1]), "r"(a[2]), "r"(a[3]), "r"(b0), "r"(b1));
}
__device__ __forceinline__ void mma16816h(float* d, const uint32_t* a, uint32_t b0, uint32_t b1) {
    asm volatile("mma.sync.aligned.m16n8k16.row.col.f32.f16.f16.f32 "
                 "{%0,%1,%2,%3}, {%4,%5,%6,%7}, {%8,%9}, {%0,%1,%2,%3};"
                 : "+f"(d[0]), "+f"(d[1]), "+f"(d[2]), "+f"(d[3])
                 : "r"(a[0]), "r"(a[1]), "r"(a[2]), "r"(a[3]), "r"(b0), "r"(b1));
}
#define CP16(dst, src) asm volatile("cp.async.cg.shared.global [%0], [%1], 16;" :: "r"(dst), "l"(src))
#define CP_COMMIT()    asm volatile("cp.async.commit_group;" ::: "memory")
#define CP_WAIT(n)     asm volatile("cp.async.wait_group %0;" :: "n"(n) : "memory")

__device__ __forceinline__ void split_bf16(float x, __nv_bfloat16& hi, __nv_bfloat16& lo) {
    hi = __float2bfloat16(x);
    lo = __float2bfloat16(x - __bfloat162float(hi));
}

// ============================================================
// K1: tiled transpose + scatter
//     mode 0: select/drop -> g_x fp16 (b,n,c)
//     mode 1: pcd -> g_ph/g_pl bf16 hi/lo (b,n,c)
// ============================================================
__global__ __launch_bounds__(256) void prep_kernel(
    const float* __restrict__ sel, const float* __restrict__ drp,
    const int* __restrict__ isel, const int* __restrict__ idrp,
    const float* __restrict__ pcd)
{
    __shared__ float S[128][33];
    __shared__ int dsts[32];
    int tx = blockIdx.x, mode = blockIdx.y, b = blockIdx.z;
    int t = threadIdx.x;

    if (mode == 0) {
        const float* src; const int* ip; int n0;
        if (tx < 32) { src = sel + (size_t)b * CIN * 1024; ip = isel; n0 = tx * 32; }
        else         { src = drp + (size_t)b * CIN * 1024; ip = idrp; n0 = tx * 32 - 1024; }
        #pragma unroll
        for (int i = 0; i < 16; ++i) {
            int idx = t + i * 256;
            int c = idx >> 5, n = idx & 31;
            S[c][n] = src[(size_t)c * 1024 + n0 + n];
        }
        if (t < 32) dsts[t] = ip[b * 1024 + n0 + t];
    } else {
        int n0 = tx * 32;
        #pragma unroll
        for (int i = 0; i < 16; ++i) {
            int idx = t + i * 256;
            int c = idx >> 5, n = idx & 31;
            S[c][n] = pcd[((size_t)b * CIN + c) * NTOT + n0 + n];
        }
        if (t < 32) dsts[t] = n0 + t;
    }
    __syncthreads();

    int n = t >> 3, cs = (t & 7) * 16;
    int dst = dsts[n];
    if (mode == 0) {
        __half* dx = g_x + ((size_t)(b * NTOT + dst)) * CIN + cs;
        __align__(16) __half hb[16];
        #pragma unroll
        for (int i = 0; i < 16; ++i) hb[i] = __float2half_rn(S[cs + i][n]);
        *(uint4*)dx       = *(uint4*)hb;
        *(uint4*)(dx + 8) = *(uint4*)(hb + 8);
    } else {
        __nv_bfloat16* dh = g_ph + ((size_t)(b * NTOT + dst)) * CIN + cs;
        __nv_bfloat16* dl = g_pl + ((size_t)(b * NTOT + dst)) * CIN + cs;
        __align__(16) __nv_bfloat16 hb[16], lb[16];
        #pragma unroll
        for (int i = 0; i < 16; ++i) split_bf16(S[cs + i][n], hb[i], lb[i]);
        *(uint4*)dh       = *(uint4*)hb;
        *(uint4*)(dh + 8) = *(uint4*)(hb + 8);
        *(uint4*)dl       = *(uint4*)lb;
        *(uint4*)(dl + 8) = *(uint4*)(lb + 8);
    }
}

// ============================================================
// K2: projections on tensor cores
//     m<3 (q/k/v): single-term fp16; m=3 (skip): 3-term bf16
// ============================================================
#define PW  0
#define PX  17408
#define PWH 0
#define PWL 17408
#define PXH 34816
#define PXL 69632
#define SMEM_PROJ 104448

__global__ __launch_bounds__(256, 2) void proj_kernel(
    const float* __restrict__ Wq, const float* __restrict__ Wk,
    const float* __restrict__ Wv, const float* __restrict__ Wskip,
    float* __restrict__ out)
{
    extern __shared__ __align__(1024) char smem[];
    uint32_t sb = smem_u32(smem);
    int tid = threadIdx.x, wid = tid >> 5, lane = tid & 31;
    int nb = blockIdx.x, ob = blockIdx.y, b = blockIdx.z;
    int m = ob >> 2, h = ob & 3;
    int p = b * NH + h;
    int mw = wid & 3, nw = wid >> 2;
    float acc[8][4] = {};

    if (m < 3) {
        // ---- fp16 single-term path ----
        const float* W = (m == 0 ? Wq : m == 1 ? Wk : Wv) + h * 64 * CIN;
        const __half* X = g_x + ((size_t)b * NTOT + nb * 128) * CIN;

        #pragma unroll
        for (int l = 0; l < 8; ++l) {
            int idx = tid + l * 256;               // 2048 float4
            int o = idx >> 5, c4 = (idx & 31) * 4;
            float4 w = *(const float4*)(W + o * 128 + c4);
            __align__(8) __half hw[4] = {
                __float2half_rn(w.x), __float2half_rn(w.y),
                __float2half_rn(w.z), __float2half_rn(w.w) };
            *(uint2*)(smem + PW + o * 272 + c4 * 2) = *(uint2*)hw;
        }
        #pragma unroll
        for (int l = 0; l < 8; ++l) {
            int idx = tid + l * 256;               // 2048 uint4
            int n = idx >> 4, u = idx & 15;
            *(uint4*)(smem + PX + n * 272 + u * 16) = ((const uint4*)(X + (size_t)n * CIN))[u];
        }
        __syncthreads();

        uint32_t wa = sb + PW + (mw * 16 + (lane & 15)) * 272 + (lane >> 4) * 16;
        uint32_t xb = sb + PX + (((lane & 7) | ((lane & 16) >> 1)) + nw * 64) * 272
                    + ((lane >> 3) & 1) * 16;
        #pragma unroll
        for (int kt = 0; kt < 8; ++kt) {
            uint32_t ah[4];
            ldsm_x4(ah[0], ah[1], ah[2], ah[3], wa + kt * 32);
            #pragma unroll
            for (int nt = 0; nt < 4; ++nt) {
                uint32_t bh[4];
                ldsm_x4(bh[0], bh[1], bh[2], bh[3], xb + nt * (16 * 272) + kt * 32);
                mma16816h(acc[2 * nt],     ah, bh[0], bh[1]);
                mma16816h(acc[2 * nt + 1], ah, bh[2], bh[3]);
            }
        }
    } else {
        // ---- bf16 3-term path (skip) ----
        const float* W = Wskip + h * 64 * CIN;
        const __nv_bfloat16* Xh = g_ph + ((size_t)b * NTOT + nb * 128) * CIN;
        const __nv_bfloat16* Xl = g_pl + ((size_t)b * NTOT + nb * 128) * CIN;

        #pragma unroll
        for (int l = 0; l < 8; ++l) {
            int idx = tid + l * 256;               // 2048 float4
            int o = idx >> 5, c4 = (idx & 31) * 4;
            float4 w = *(const float4*)(W + o * 128 + c4);
            __nv_bfloat16 h0, h1, h2, h3, l0, l1, l2, l3;
            split_bf16(w.x, h0, l0); split_bf16(w.y, h1, l1);
            split_bf16(w.z, h2, l2); split_bf16(w.w, h3, l3);
            __nv_bfloat162* dh = (__nv_bfloat162*)(smem + PWH + o * 272 + c4 * 2);
            __nv_bfloat162* dl = (__nv_bfloat162*)(smem + PWL + o * 272 + c4 * 2);
            dh[0] = {h0, h1}; dh[1] = {h2, h3};
            dl[0] = {l0, l1}; dl[1] = {l2, l3};
        }
        #pragma unroll
        for (int l = 0; l < 8; ++l) {
            int idx = tid + l * 256;               // 2048 uint4
            int n = idx >> 4, u = idx & 15;
            *(uint4*)(smem + PXH + n * 272 + u * 16) = ((const uint4*)(Xh + (size_t)n * CIN))[u];
            *(uint4*)(smem + PXL + n * 272 + u * 16) = ((const uint4*)(Xl + (size_t)n * CIN))[u];
        }
        __syncthreads();

        uint32_t wa = sb + PWH + (mw * 16 + (lane & 15)) * 272 + (lane >> 4) * 16;
        uint32_t xb = sb + PXH + (((lane & 7) | ((lane & 16) >> 1)) + nw * 64) * 272
                    + ((lane >> 3) & 1) * 16;
        #pragma unroll
        for (int kt = 0; kt < 8; ++kt) {
            uint32_t ah[4], al[4];
            ldsm_x4(ah[0], ah[1], ah[2], ah[3], wa + kt * 32);
            ldsm_x4(al[0], al[1], al[2], al[3], wa + (PWL - PWH) + kt * 32);
            #pragma unroll
            for (int nt = 0; nt < 4; ++nt) {
                uint32_t bh[4], bl[4];
                uint32_t base = xb + nt * (16 * 272) + kt * 32;
                ldsm_x4(bh[0], bh[1], bh[2], bh[3], base);
                ldsm_x4(bl[0], bl[1], bl[2], bl[3], base + (PXL - PXH));
                mma16816(acc[2 * nt],     ah, bh[0], bh[1]);
                mma16816(acc[2 * nt + 1], ah, bh[2], bh[3]);
                mma16816(acc[2 * nt],     al, bh[0], bh[1]);
                mma16816(acc[2 * nt + 1], al, bh[2], bh[3]);
                mma16816(acc[2 * nt],     ah, bl[0], bl[1]);
                mma16816(acc[2 * nt + 1], ah, bl[2], bl[3]);
            }
        }
    }

    if (m == 3) {                                  // skip -> d_out (fp32)
        #pragma unroll
        for (int g = 0; g < 8; ++g) {
            int n_g = nb * 128 + nw * 64 + g * 8 + (lane & 3) * 2;
            #pragma unroll
            for (int cc = 0; cc < 2; ++cc) {
                int o_g = h * 64 + mw * 16 + (lane >> 2) + cc * 8;
                float2 st = {acc[g][2 * cc], acc[g][2 * cc + 1]};
                *(float2*)(out + ((size_t)(b * OUTC + o_g)) * NTOT + n_g) = st;
            }
        }
    } else {                                       // q/k/v: stage [n][d] fp16 pitch 72h -> (p,n,d)
        float scale = (m == 0) ? 0.125f : 1.0f;
        __syncthreads();
        __half* S = (__half*)smem;
        #pragma unroll
        for (int g = 0; g < 8; ++g) {
            int n0 = nw * 64 + g * 8 + (lane & 3) * 2;
            #pragma unroll
            for (int cc = 0; cc < 2; ++cc) {
                int d = mw * 16 + (lane >> 2) + cc * 8;
                #pragma unroll
                for (int e = 0; e < 2; ++e)
                    S[(n0 + e) * 72 + d] = __float2half_rn(acc[g][2 * cc + e] * scale);
            }
        }
        __syncthreads();
        __half* dst = (m == 0 ? g_q : m == 1 ? g_k : g_v) + ((size_t)p * NTOT + nb * 128) * HD;
        #pragma unroll
        for (int l = 0; l < 4; ++l) {
            int idx = tid + l * 256;               // 1024 uint4 (128 rows x 128 B)
            int n = idx >> 3, u = idx & 7;
            ((uint4*)dst)[idx] = *(const uint4*)((char*)S + n * 144 + u * 16);
        }
    }
}

// ============================================================
// K3: fused flash attention, single-term fp16 HMMA
//     4 warps x M=32 = 128 rows/CTA, 2 CTAs/SM, grid (16 it, 16 p)
// ============================================================
#define PIT 144
#define AQ  0
#define AK0 18432
#define AK1 27648
#define AV0 36864
#define AV1 46080
#define SMEM_ATTN 55296

__device__ __forceinline__ void load_kv(uint32_t sb, int p, int c, int s, int tid) {
    const char* gk = (const char*)(g_k + ((size_t)p * NTOT + c * 64) * HD);
    const char* gv = (const char*)(g_v + ((size_t)p * NTOT + c * 64) * HD);
    uint32_t kd = sb + (s ? AK1 : AK0);
    uint32_t vd = sb + (s ? AV1 : AV0);
    #pragma unroll
    for (int l = 0; l < 4; ++l) {
        int idx = tid + l * 128;                   // 512 x 16B each
        int row = idx >> 3, c16 = (idx & 7) * 16;
        CP16(kd + row * PIT + c16, gk + row * 128 + c16);
        CP16(vd + row * PIT + c16, gv + row * 128 + c16);
    }
}

__global__ __launch_bounds__(128, 2) void attn_kernel(float* __restrict__ out)
{
    extern __shared__ __align__(1024) char smem[];
    uint32_t sb = smem_u32(smem);
    int tid = threadIdx.x, wid = tid >> 5, lane = tid & 31;
    int g = lane >> 2, t = lane & 3;
    int it = blockIdx.x, p = blockIdx.y;
    int b = p >> 2, h = p & 3;

    // ---- issue Q (128 rows x 128B) + chunk0 as group 0 ----
    {
        const char* gq = (const char*)(g_q + ((size_t)p * NTOT + it * 128) * HD);
        #pragma unroll
        for (int l = 0; l < 8; ++l) {
            int idx = tid + l * 128;               // 1024 x 16B
            int row = idx >> 3, c16 = (idx & 7) * 16;
            CP16(sb + AQ + row * PIT + c16, gq + row * 128 + c16);
        }
        load_kv(sb, p, 0, 0, tid);
        CP_COMMIT();
    }

    uint32_t qa = sb + AQ + (wid * 32 + (lane & 15)) * PIT + (lane >> 4) * 16;
    uint32_t kb_rel = ((lane & 7) | ((lane & 16) >> 1)) * PIT + ((lane >> 3) & 1) * 16;
    uint32_t vb_rel = (lane & 15) * PIT + (lane >> 4) * 16;

    float o[2][8][4] = {};
    float rs[2][2] = {};

    for (int c = 0; c < NCHUNK; ++c) {
        if (c) __syncthreads();
        if (c < NCHUNK - 1) {
            load_kv(sb, p, c + 1, (c + 1) & 1, tid);
            CP_COMMIT();
            CP_WAIT(1);
        } else {
            CP_WAIT(0);
        }
        __syncthreads();

        uint32_t kb = sb + ((c & 1) ? AK1 : AK0) + kb_rel;
        uint32_t vb = sb + ((c & 1) ? AV1 : AV0) + vb_rel;

        // ---- S = Q Kᵀ (single-term fp16) ----
        float s[2][8][4] = {};
        #pragma unroll
        for (int kt = 0; kt < 4; ++kt) {
            uint32_t aq[2][4];
            #pragma unroll
            for (int mi = 0; mi < 2; ++mi)
                ldsm_x4(aq[mi][0], aq[mi][1], aq[mi][2], aq[mi][3],
                        qa + mi * (16 * PIT) + kt * 32);
            #pragma unroll
            for (int nt2 = 0; nt2 < 4; ++nt2) {
                uint32_t bh[4];
                ldsm_x4(bh[0], bh[1], bh[2], bh[3], kb + nt2 * (16 * PIT) + kt * 32);
                #pragma unroll
                for (int mi = 0; mi < 2; ++mi) {
                    mma16816h(s[mi][2 * nt2],     aq[mi], bh[0], bh[1]);
                    mma16816h(s[mi][2 * nt2 + 1], aq[mi], bh[2], bh[3]);
                }
            }
        }

        // ---- per-kt: exp + fp16 pack, then P·V (V via trans-ldmatrix) ----
        #pragma unroll
        for (int kt = 0; kt < 4; ++kt) {
            uint32_t ph[2][4];
            #pragma unroll
            for (int mi = 0; mi < 2; ++mi) {
                #pragma unroll
                for (int hf = 0; hf < 2; ++hf) {
                    float* sv = s[mi][2 * kt + hf];
                    float e0 = __expf(sv[0]), e1 = __expf(sv[1]);
                    float e2 = __expf(sv[2]), e3 = __expf(sv[3]);
                    rs[mi][0] += e0 + e1; rs[mi][1] += e2 + e3;
                    uint32_t h01, h23;
                    asm("cvt.rn.f16x2.f32 %0, %1, %2;" : "=r"(h01) : "f"(e1), "f"(e0));
                    asm("cvt.rn.f16x2.f32 %0, %1, %2;" : "=r"(h23) : "f"(e3), "f"(e2));
                    ph[mi][2 * hf] = h01; ph[mi][2 * hf + 1] = h23;
                }
            }
            #pragma unroll
            for (int nt2 = 0; nt2 < 4; ++nt2) {
                uint32_t bh[4];
                ldsm_x4_t(bh[0], bh[1], bh[2], bh[3], vb + kt * (16 * PIT) + nt2 * 32);
                #pragma unroll
                for (int mi = 0; mi < 2; ++mi) {
                    mma16816h(o[mi][2 * nt2],     ph[mi], bh[0], bh[1]);
                    mma16816h(o[mi][2 * nt2 + 1], ph[mi], bh[2], bh[3]);
                }
            }
        }
    }

    // ---- rowsum reduce across quad, normalize, transpose via smem ----
    float inv[2][2];
    #pragma unroll
    for (int mi = 0; mi < 2; ++mi) {
        #pragma unroll
        for (int cc = 0; cc < 2; ++cc) {
            float v = rs[mi][cc];
            v += __shfl_xor_sync(0xffffffffu, v, 1);
            v += __shfl_xor_sync(0xffffffffu, v, 2);
            inv[mi][cc] = 1.0f / v;
        }
    }

    __syncthreads();
    float* Os = (float*)smem;                      // [64][129]
    #pragma unroll
    for (int mi = 0; mi < 2; ++mi) {
        int i0 = wid * 32 + mi * 16 + g;
        #pragma unroll
        for (int dt = 0; dt < 8; ++dt) {
            int d0 = dt * 8 + t * 2;
            Os[d0 * 129 + i0]           = o[mi][dt][0] * inv[mi][0];
            Os[(d0 + 1) * 129 + i0]     = o[mi][dt][1] * inv[mi][0];
            Os[d0 * 129 + i0 + 8]       = o[mi][dt][2] * inv[mi][1];
            Os[(d0 + 1) * 129 + i0 + 8] = o[mi][dt][3] * inv[mi][1];
        }
    }
    __syncthreads();

    #pragma unroll
    for (int l = 0; l < 64; ++l) {
        int idx = tid + l * 128;                   // 8192 elements
        int i = idx & 127, d = idx >> 7;
        size_t go = ((size_t)(b * OUTC + h * HD + d)) * NTOT + it * 128 + i;
        out[go] += Os[d * 129 + i];
    }
}

// ============================================================
extern "C" void kernel_launch(void* const* d_in, const int* in_sizes, int n_in,
                              void* d_out, int out_size)
{
    const float* pcd   = (const float*)d_in[0];
    const float* sel   = (const float*)d_in[1];
    const float* drp   = (const float*)d_in[2];
    const int*   isel  = (const int*)d_in[3];
    const int*   idrp  = (const int*)d_in[4];
    const float* Wq    = (const float*)d_in[5];
    const float* Wk    = (const float*)d_in[6];
    const float* Wv    = (const float*)d_in[7];
    const float* Wskip = (const float*)d_in[8];
    float* out = (float*)d_out;

    cudaFuncSetAttribute(proj_kernel, cudaFuncAttributeMaxDynamicSharedMemorySize, SMEM_PROJ);
    cudaFuncSetAttribute(attn_kernel, cudaFuncAttributeMaxDynamicSharedMemorySize, SMEM_ATTN);

    prep_kernel<<<dim3(64, 2, NB), 256>>>(sel, drp, isel, idrp, pcd);
    proj_kernel<<<dim3(16, 16, NB), 256, SMEM_PROJ>>>(Wq, Wk, Wv, Wskip, out);
    attn_kernel<<<dim3(16, NP), 128, SMEM_ATTN>>>(out);
}